// round 1
// baseline (speedup 1.0000x reference)
#include <cuda_runtime.h>
#include <math.h>

#define BB   2
#define TT   4096
#define CC   512
#define HH   8
#define DD   64
#define MEMW 256

#define M_TOT (BB*TT)     // 8192
#define QKVN  (3*CC)      // 1536

// scratch (allocation-free contract: device globals)
__device__ float g_qkv[BB*TT*3*CC];   // [B*T, 3C]
__device__ float g_y[BB*TT*CC];       // [B*T, C]

// ---------------------------------------------------------------------------
// GEMM (NT): C[m,n] = sum_k A[m,k] * W[n,k]
// 64x64 tile, BK=32, 256 threads, 4x4 microtile, float4 smem fragments
// ---------------------------------------------------------------------------
template<int BM, int BN, int BK>
__global__ __launch_bounds__(256) void gemm_nt(const float* __restrict__ A,
                                               const float* __restrict__ W,
                                               float* __restrict__ Cout,
                                               int M, int N, int K) {
    __shared__ float As[BK][BM + 4];
    __shared__ float Bs[BK][BN + 4];
    const int tx = threadIdx.x & 15;
    const int ty = threadIdx.x >> 4;
    const int m0 = blockIdx.y * BM;
    const int n0 = blockIdx.x * BN;

    float acc[4][4] = {};

    for (int k0 = 0; k0 < K; k0 += BK) {
        // load A tile (BM x BK) transposed -> As[k][m]
        for (int i = threadIdx.x; i < BM * (BK / 4); i += 256) {
            int row = i / (BK / 4);
            int kc4 = (i % (BK / 4)) * 4;
            float4 v = *(const float4*)&A[(size_t)(m0 + row) * K + k0 + kc4];
            As[kc4 + 0][row] = v.x;
            As[kc4 + 1][row] = v.y;
            As[kc4 + 2][row] = v.z;
            As[kc4 + 3][row] = v.w;
        }
        // load W tile (BN x BK) transposed -> Bs[k][n]
        for (int i = threadIdx.x; i < BN * (BK / 4); i += 256) {
            int row = i / (BK / 4);
            int kc4 = (i % (BK / 4)) * 4;
            float4 v = *(const float4*)&W[(size_t)(n0 + row) * K + k0 + kc4];
            Bs[kc4 + 0][row] = v.x;
            Bs[kc4 + 1][row] = v.y;
            Bs[kc4 + 2][row] = v.z;
            Bs[kc4 + 3][row] = v.w;
        }
        __syncthreads();

        #pragma unroll 16
        for (int kk = 0; kk < BK; kk++) {
            float4 a = *(const float4*)&As[kk][ty * 4];
            float4 b = *(const float4*)&Bs[kk][tx * 4];
            float av[4] = {a.x, a.y, a.z, a.w};
            float bv[4] = {b.x, b.y, b.z, b.w};
            #pragma unroll
            for (int i = 0; i < 4; i++)
                #pragma unroll
                for (int j = 0; j < 4; j++)
                    acc[i][j] = fmaf(av[i], bv[j], acc[i][j]);
        }
        __syncthreads();
    }

    #pragma unroll
    for (int i = 0; i < 4; i++) {
        float4 v = make_float4(acc[i][0], acc[i][1], acc[i][2], acc[i][3]);
        *(float4*)&Cout[(size_t)(m0 + ty * 4 + i) * N + n0 + tx * 4] = v;
    }
}

// ---------------------------------------------------------------------------
// Sliding-window attention.
// One block = 64 queries of one (b,h). Keys live in [q0-256, q0+63] = 5 tiles
// of 64. Two-pass: full 64x320 score strip in smem -> softmax -> P.V.
// ---------------------------------------------------------------------------
#define QT 64
#define KT 64
#define NKT 5
#define NK  (NKT*KT)      // 320
#define SPITCH 324        // NK + 4 (float4 alignment)
#define TPITCH 68         // tile pitch (64 + 4)

// smem floats: Qs 64*68 + KVs 64*68 + S 64*324 + red 256 + rowsum 64
#define ATTN_SMEM_FLOATS (DD*TPITCH + KT*TPITCH + QT*SPITCH + 256 + 64)

__global__ __launch_bounds__(256) void attn_kernel(const float* __restrict__ qkv,
                                                   float* __restrict__ y) {
    extern __shared__ float sh[];
    float* Qs     = sh;                       // [DD][TPITCH] transposed: Qs[dd][q]
    float* KVs    = Qs + DD * TPITCH;         // scores: Ks[dd][k]; PV: Vs[kk][dd]
    float* S      = KVs + KT * TPITCH;        // [QT][SPITCH]
    float* red    = S + QT * SPITCH;          // [64][4]
    float* rowsum = red + 256;                // [64]

    const int tid = threadIdx.x;
    const int tx = tid & 15;
    const int ty = tid >> 4;
    const int q0 = blockIdx.x * QT;
    const int h  = blockIdx.y;
    const int b  = blockIdx.z;
    const int kstart = q0 - MEMW;

    const float* qbase = qkv + (size_t)b * TT * QKVN + h * DD;
    const float* kbase = qbase + CC;
    const float* vbase = qbase + 2 * CC;

    // load Q tile transposed: Qs[dd][q]
    for (int i = tid; i < QT * (DD / 4); i += 256) {
        int q  = i / (DD / 4);
        int d4 = (i % (DD / 4)) * 4;
        float4 v = *(const float4*)&qbase[(size_t)(q0 + q) * QKVN + d4];
        Qs[(d4 + 0) * TPITCH + q] = v.x;
        Qs[(d4 + 1) * TPITCH + q] = v.y;
        Qs[(d4 + 2) * TPITCH + q] = v.z;
        Qs[(d4 + 3) * TPITCH + q] = v.w;
    }

    // ---- scores phase: S[q][k] for all 5 key tiles ----
    for (int kt = 0; kt < NKT; kt++) {
        __syncthreads();   // Q ready (first iter) / prev compute done with KVs
        const int kb = kstart + kt * KT;
        // load K tile transposed: Ks[dd][k]
        for (int i = tid; i < KT * (DD / 4); i += 256) {
            int kk = i / (DD / 4);
            int d4 = (i % (DD / 4)) * 4;
            int g  = kb + kk;
            float4 v = make_float4(0.f, 0.f, 0.f, 0.f);
            if (g >= 0) v = *(const float4*)&kbase[(size_t)g * QKVN + d4];
            KVs[(d4 + 0) * TPITCH + kk] = v.x;
            KVs[(d4 + 1) * TPITCH + kk] = v.y;
            KVs[(d4 + 2) * TPITCH + kk] = v.z;
            KVs[(d4 + 3) * TPITCH + kk] = v.w;
        }
        __syncthreads();

        float acc[4][4] = {};
        #pragma unroll 16
        for (int dd = 0; dd < DD; dd++) {
            float4 a = *(const float4*)&Qs[dd * TPITCH + ty * 4];
            float4 bb = *(const float4*)&KVs[dd * TPITCH + tx * 4];
            float av[4] = {a.x, a.y, a.z, a.w};
            float bv[4] = {bb.x, bb.y, bb.z, bb.w};
            #pragma unroll
            for (int i = 0; i < 4; i++)
                #pragma unroll
                for (int j = 0; j < 4; j++)
                    acc[i][j] = fmaf(av[i], bv[j], acc[i][j]);
        }
        // masked, scaled store
        #pragma unroll
        for (int i = 0; i < 4; i++) {
            int qi = q0 + ty * 4 + i;
            #pragma unroll
            for (int j = 0; j < 4; j++) {
                int kj = kb + tx * 4 + j;
                bool ok = (kj >= 0) && (kj <= qi) && (qi - kj <= MEMW);
                S[(ty * 4 + i) * SPITCH + kt * KT + tx * 4 + j] =
                    ok ? acc[i][j] * 0.125f : -1e30f;
            }
        }
    }
    __syncthreads();

    // ---- softmax: 4 threads per row ----
    {
        int r = tid >> 2;
        int s = tid & 3;
        float mx = -1e30f;
        for (int c = s; c < NK; c += 4) mx = fmaxf(mx, S[r * SPITCH + c]);
        red[r * 4 + s] = mx;
        __syncthreads();
        mx = fmaxf(fmaxf(red[r * 4 + 0], red[r * 4 + 1]),
                   fmaxf(red[r * 4 + 2], red[r * 4 + 3]));
        __syncthreads();                 // all reads of red done before reuse
        float sum = 0.f;
        for (int c = s; c < NK; c += 4) {
            float e = __expf(S[r * SPITCH + c] - mx);
            S[r * SPITCH + c] = e;
            sum += e;
        }
        red[r * 4 + s] = sum;
        __syncthreads();
        if (s == 0)
            rowsum[r] = red[r * 4 + 0] + red[r * 4 + 1] +
                        red[r * 4 + 2] + red[r * 4 + 3];
    }

    // ---- PV phase ----
    float oacc[4][4] = {};
    for (int kt = 0; kt < NKT; kt++) {
        __syncthreads();   // S/softmax done (first iter) / prev compute done with KVs
        const int kb = kstart + kt * KT;
        // load V tile natural: Vs[kk][dd]
        for (int i = tid; i < KT * (DD / 4); i += 256) {
            int kk = i / (DD / 4);
            int d4 = (i % (DD / 4)) * 4;
            int g  = kb + kk;
            float4 v = make_float4(0.f, 0.f, 0.f, 0.f);
            if (g >= 0) v = *(const float4*)&vbase[(size_t)g * QKVN + d4];
            *(float4*)&KVs[kk * TPITCH + d4] = v;
        }
        __syncthreads();

        #pragma unroll 8
        for (int kk = 0; kk < KT; kk++) {
            float4 bb = *(const float4*)&KVs[kk * TPITCH + tx * 4];
            float bv[4] = {bb.x, bb.y, bb.z, bb.w};
            float av[4];
            #pragma unroll
            for (int i = 0; i < 4; i++)
                av[i] = S[(ty * 4 + i) * SPITCH + kt * KT + kk];
            #pragma unroll
            for (int i = 0; i < 4; i++)
                #pragma unroll
                for (int j = 0; j < 4; j++)
                    oacc[i][j] = fmaf(av[i], bv[j], oacc[i][j]);
        }
    }
    __syncthreads();

    // epilogue: normalize and store y[b,t,h*64+dd]
    #pragma unroll
    for (int i = 0; i < 4; i++) {
        int q = q0 + ty * 4 + i;
        float inv = 1.0f / rowsum[ty * 4 + i];
        float4 v = make_float4(oacc[i][0] * inv, oacc[i][1] * inv,
                               oacc[i][2] * inv, oacc[i][3] * inv);
        *(float4*)&y[(size_t)(b * TT + q) * CC + h * DD + tx * 4] = v;
    }
}

// ---------------------------------------------------------------------------
extern "C" void kernel_launch(void* const* d_in, const int* in_sizes, int n_in,
                              void* d_out, int out_size) {
    const float* x      = (const float*)d_in[0];
    const float* w_attn = (const float*)d_in[1];
    const float* w_proj = (const float*)d_in[2];
    float* out = (float*)d_out;

    float* qkv = nullptr;
    float* yb  = nullptr;
    cudaGetSymbolAddress((void**)&qkv, g_qkv);
    cudaGetSymbolAddress((void**)&yb,  g_y);

    const int attn_smem = ATTN_SMEM_FLOATS * (int)sizeof(float);
    cudaFuncSetAttribute(attn_kernel,
                         cudaFuncAttributeMaxDynamicSharedMemorySize, attn_smem);

    // 1) QKV projection: qkv = x @ w_attn^T   [8192,1536]
    {
        dim3 grid(QKVN / 64, M_TOT / 64);
        gemm_nt<64, 64, 32><<<grid, 256>>>(x, w_attn, qkv, M_TOT, QKVN, CC);
    }
    // 2) windowed attention -> y [8192,512]
    {
        dim3 grid(TT / QT, HH, BB);
        attn_kernel<<<grid, 256, attn_smem>>>(qkv, yb);
    }
    // 3) output projection: out = y @ w_proj^T  [8192,512]
    {
        dim3 grid(CC / 64, M_TOT / 64);
        gemm_nt<64, 64, 32><<<grid, 256>>>(yb, w_proj, out, M_TOT, CC, CC);
    }
}

// round 3
// speedup vs baseline: 1.8874x; 1.8874x over previous
#include <cuda_runtime.h>
#include <math.h>
#include <stdint.h>

#define BB   2
#define TT   4096
#define CC   512
#define HH   8
#define DD   64
#define MEMW 256

#define M_TOT (BB*TT)     // 8192
#define QKVN  (3*CC)      // 1536

// scratch (allocation-free contract: device globals)
__device__ float g_qkv[BB*TT*3*CC];   // [B*T, 3C]
__device__ float g_y[BB*TT*CC];       // [B*T, C]

// ===========================================================================
// helpers
// ===========================================================================
__device__ __forceinline__ uint32_t smem_u32(const void* p) {
    uint32_t a;
    asm("{ .reg .u64 t; cvta.to.shared.u64 t, %1; cvt.u32.u64 %0, t; }"
        : "=r"(a) : "l"(p));
    return a;
}
__device__ __forceinline__ uint32_t f2tf32(float f) {
    uint32_t r;
    asm("cvt.rna.tf32.f32 %0, %1;" : "=r"(r) : "f"(f));
    return r;
}
#define SW128(off) ((off) ^ (((off) >> 3) & 0x70))

#define LDSM_X4(r0, r1, r2, r3, addr) \
    asm volatile("ldmatrix.sync.aligned.m8n8.x4.shared.b16 {%0,%1,%2,%3}, [%4];" \
                 : "=r"(r0), "=r"(r1), "=r"(r2), "=r"(r3) : "r"(addr))

#define MMA_TF32(c, a0, a1, a2, a3, b0, b1) \
    asm volatile("mma.sync.aligned.m16n8k8.row.col.f32.tf32.tf32.f32 " \
                 "{%0,%1,%2,%3}, {%4,%5,%6,%7}, {%8,%9}, {%0,%1,%2,%3};" \
                 : "+f"((c)[0]), "+f"((c)[1]), "+f"((c)[2]), "+f"((c)[3]) \
                 : "r"(a0), "r"(a1), "r"(a2), "r"(a3), "r"(b0), "r"(b1))

// ===========================================================================
// tf32 mma.sync GEMM (NT): C[m,n] = sum_k A[m,k] * W[n,k]
// CTA tile 128x128, BK=32, 8 warps (4m x 2n), warp tile 32x64.
// smem tiles SW128-swizzled, fragments via ldmatrix.x4.
// ===========================================================================
#define GBM 128
#define GBN 128
#define GBK 32

__global__ __launch_bounds__(256) void gemm_mma(const float* __restrict__ A,
                                                const float* __restrict__ W,
                                                float* __restrict__ Cout,
                                                int M, int N, int K) {
    __shared__ float smA[GBM * GBK];   // [128][32] rows of 128B, swizzled
    __shared__ float smB[GBN * GBK];

    const int tid  = threadIdx.x;
    const int lane = tid & 31;
    const int wid  = tid >> 5;
    const int wm   = wid & 3;          // 4 warps along M
    const int wn   = wid >> 2;         // 2 warps along N
    const int m0 = blockIdx.y * GBM;
    const int n0 = blockIdx.x * GBN;

    const uint32_t sA = smem_u32(smA);
    const uint32_t sB = smem_u32(smB);

    float acc[2][8][4];
    #pragma unroll
    for (int i = 0; i < 2; i++)
        #pragma unroll
        for (int j = 0; j < 8; j++)
            #pragma unroll
            for (int k = 0; k < 4; k++) acc[i][j][k] = 0.f;

    // precomputed ldmatrix lane geometry
    const int a_row_in = (lane & 15);             // + fm*16
    const int a_c16_in = (lane >> 4);             // + ks*2
    const int b_row_in = (lane & 7) + ((lane >> 4) << 3);   // + g*16
    const int b_c16_in = ((lane >> 3) & 1);       // + ks*2

    const int nk = K / GBK;
    for (int kt = 0; kt < nk; kt++) {
        const int k0 = kt * GBK;

        // ---- load A,B tiles (each 128x32 f32), cvt->tf32, swizzled store ----
        #pragma unroll
        for (int it = 0; it < 4; it++) {
            int i = tid + it * 256;
            int row = i >> 3;
            int c16 = i & 7;
            float4 v = *(const float4*)&A[(size_t)(m0 + row) * K + k0 + c16 * 4];
            uint32_t byte = SW128((uint32_t)(row * 128 + c16 * 16));
            *(uint4*)((char*)smA + byte) =
                make_uint4(f2tf32(v.x), f2tf32(v.y), f2tf32(v.z), f2tf32(v.w));
        }
        #pragma unroll
        for (int it = 0; it < 4; it++) {
            int i = tid + it * 256;
            int row = i >> 3;
            int c16 = i & 7;
            float4 v = *(const float4*)&W[(size_t)(n0 + row) * K + k0 + c16 * 4];
            uint32_t byte = SW128((uint32_t)(row * 128 + c16 * 16));
            *(uint4*)((char*)smB + byte) =
                make_uint4(f2tf32(v.x), f2tf32(v.y), f2tf32(v.z), f2tf32(v.w));
        }
        __syncthreads();

        // ---- 4 k-steps of k=8 ----
        #pragma unroll
        for (int ks = 0; ks < 4; ks++) {
            uint32_t a[2][4];
            #pragma unroll
            for (int fm = 0; fm < 2; fm++) {
                int row = wm * 32 + fm * 16 + a_row_in;
                int c16 = ks * 2 + a_c16_in;
                uint32_t addr = sA + SW128((uint32_t)(row * 128 + c16 * 16));
                LDSM_X4(a[fm][0], a[fm][1], a[fm][2], a[fm][3], addr);
            }
            uint32_t b[4][4];
            #pragma unroll
            for (int g = 0; g < 4; g++) {
                int row = wn * 64 + g * 16 + b_row_in;
                int c16 = ks * 2 + b_c16_in;
                uint32_t addr = sB + SW128((uint32_t)(row * 128 + c16 * 16));
                LDSM_X4(b[g][0], b[g][1], b[g][2], b[g][3], addr);
            }
            #pragma unroll
            for (int fm = 0; fm < 2; fm++)
                #pragma unroll
                for (int fn = 0; fn < 8; fn++) {
                    const int bg = fn >> 1;
                    if (fn & 1) {
                        MMA_TF32(acc[fm][fn], a[fm][0], a[fm][1], a[fm][2], a[fm][3],
                                 b[bg][2], b[bg][3]);
                    } else {
                        MMA_TF32(acc[fm][fn], a[fm][0], a[fm][1], a[fm][2], a[fm][3],
                                 b[bg][0], b[bg][1]);
                    }
                }
        }
        __syncthreads();
    }

    // ---- epilogue: c0,c1 at (g, 2c),(g,2c+1); c2,c3 at (g+8, ...) ----
    const int g = lane >> 2;
    const int cpair = (lane & 3) * 2;
    #pragma unroll
    for (int fm = 0; fm < 2; fm++) {
        #pragma unroll
        for (int fn = 0; fn < 8; fn++) {
            int r = m0 + wm * 32 + fm * 16 + g;
            int c = n0 + wn * 64 + fn * 8 + cpair;
            *(float2*)&Cout[(size_t)r * N + c] =
                make_float2(acc[fm][fn][0], acc[fm][fn][1]);
            *(float2*)&Cout[(size_t)(r + 8) * N + c] =
                make_float2(acc[fm][fn][2], acc[fm][fn][3]);
        }
    }
}

// ===========================================================================
// Sliding-window attention (fp32 SIMT, unchanged from R1 passing version)
// ===========================================================================
#define QT 64
#define KT 64
#define NKT 5
#define NK  (NKT*KT)      // 320
#define SPITCH 324
#define TPITCH 68

#define ATTN_SMEM_FLOATS (DD*TPITCH + KT*TPITCH + QT*SPITCH + 256 + 64)

__global__ __launch_bounds__(256) void attn_kernel(const float* __restrict__ qkv,
                                                   float* __restrict__ y) {
    extern __shared__ float sh[];
    float* Qs     = sh;
    float* KVs    = Qs + DD * TPITCH;
    float* S      = KVs + KT * TPITCH;
    float* red    = S + QT * SPITCH;
    float* rowsum = red + 256;

    const int tid = threadIdx.x;
    const int tx = tid & 15;
    const int ty = tid >> 4;
    const int q0 = blockIdx.x * QT;
    const int h  = blockIdx.y;
    const int b  = blockIdx.z;
    const int kstart = q0 - MEMW;

    const float* qbase = qkv + (size_t)b * TT * QKVN + h * DD;
    const float* kbase = qbase + CC;
    const float* vbase = qbase + 2 * CC;

    for (int i = tid; i < QT * (DD / 4); i += 256) {
        int q  = i / (DD / 4);
        int d4 = (i % (DD / 4)) * 4;
        float4 v = *(const float4*)&qbase[(size_t)(q0 + q) * QKVN + d4];
        Qs[(d4 + 0) * TPITCH + q] = v.x;
        Qs[(d4 + 1) * TPITCH + q] = v.y;
        Qs[(d4 + 2) * TPITCH + q] = v.z;
        Qs[(d4 + 3) * TPITCH + q] = v.w;
    }

    for (int kt = 0; kt < NKT; kt++) {
        __syncthreads();
        const int kb = kstart + kt * KT;
        for (int i = tid; i < KT * (DD / 4); i += 256) {
            int kk = i / (DD / 4);
            int d4 = (i % (DD / 4)) * 4;
            int g  = kb + kk;
            float4 v = make_float4(0.f, 0.f, 0.f, 0.f);
            if (g >= 0) v = *(const float4*)&kbase[(size_t)g * QKVN + d4];
            KVs[(d4 + 0) * TPITCH + kk] = v.x;
            KVs[(d4 + 1) * TPITCH + kk] = v.y;
            KVs[(d4 + 2) * TPITCH + kk] = v.z;
            KVs[(d4 + 3) * TPITCH + kk] = v.w;
        }
        __syncthreads();

        float acc[4][4] = {};
        #pragma unroll 16
        for (int dd = 0; dd < DD; dd++) {
            float4 a = *(const float4*)&Qs[dd * TPITCH + ty * 4];
            float4 bb = *(const float4*)&KVs[dd * TPITCH + tx * 4];
            float av[4] = {a.x, a.y, a.z, a.w};
            float bv[4] = {bb.x, bb.y, bb.z, bb.w};
            #pragma unroll
            for (int i = 0; i < 4; i++)
                #pragma unroll
                for (int j = 0; j < 4; j++)
                    acc[i][j] = fmaf(av[i], bv[j], acc[i][j]);
        }
        #pragma unroll
        for (int i = 0; i < 4; i++) {
            int qi = q0 + ty * 4 + i;
            #pragma unroll
            for (int j = 0; j < 4; j++) {
                int kj = kb + tx * 4 + j;
                bool ok = (kj >= 0) && (kj <= qi) && (qi - kj <= MEMW);
                S[(ty * 4 + i) * SPITCH + kt * KT + tx * 4 + j] =
                    ok ? acc[i][j] * 0.125f : -1e30f;
            }
        }
    }
    __syncthreads();

    {
        int r = tid >> 2;
        int s = tid & 3;
        float mx = -1e30f;
        for (int c = s; c < NK; c += 4) mx = fmaxf(mx, S[r * SPITCH + c]);
        red[r * 4 + s] = mx;
        __syncthreads();
        mx = fmaxf(fmaxf(red[r * 4 + 0], red[r * 4 + 1]),
                   fmaxf(red[r * 4 + 2], red[r * 4 + 3]));
        __syncthreads();
        float sum = 0.f;
        for (int c = s; c < NK; c += 4) {
            float e = __expf(S[r * SPITCH + c] - mx);
            S[r * SPITCH + c] = e;
            sum += e;
        }
        red[r * 4 + s] = sum;
        __syncthreads();
        if (s == 0)
            rowsum[r] = red[r * 4 + 0] + red[r * 4 + 1] +
                        red[r * 4 + 2] + red[r * 4 + 3];
    }

    float oacc[4][4] = {};
    for (int kt = 0; kt < NKT; kt++) {
        __syncthreads();
        const int kb = kstart + kt * KT;
        for (int i = tid; i < KT * (DD / 4); i += 256) {
            int kk = i / (DD / 4);
            int d4 = (i % (DD / 4)) * 4;
            int g  = kb + kk;
            float4 v = make_float4(0.f, 0.f, 0.f, 0.f);
            if (g >= 0) v = *(const float4*)&vbase[(size_t)g * QKVN + d4];
            *(float4*)&KVs[kk * TPITCH + d4] = v;
        }
        __syncthreads();

        #pragma unroll 8
        for (int kk = 0; kk < KT; kk++) {
            float4 bb = *(const float4*)&KVs[kk * TPITCH + tx * 4];
            float bv[4] = {bb.x, bb.y, bb.z, bb.w};
            float av[4];
            #pragma unroll
            for (int i = 0; i < 4; i++)
                av[i] = S[(ty * 4 + i) * SPITCH + kt * KT + kk];
            #pragma unroll
            for (int i = 0; i < 4; i++)
                #pragma unroll
                for (int j = 0; j < 4; j++)
                    oacc[i][j] = fmaf(av[i], bv[j], oacc[i][j]);
        }
    }
    __syncthreads();

    #pragma unroll
    for (int i = 0; i < 4; i++) {
        int q = q0 + ty * 4 + i;
        float inv = 1.0f / rowsum[ty * 4 + i];
        float4 v = make_float4(oacc[i][0] * inv, oacc[i][1] * inv,
                               oacc[i][2] * inv, oacc[i][3] * inv);
        *(float4*)&y[(size_t)(b * TT + q) * CC + h * DD + tx * 4] = v;
    }
}

// ===========================================================================
extern "C" void kernel_launch(void* const* d_in, const int* in_sizes, int n_in,
                              void* d_out, int out_size) {
    const float* x      = (const float*)d_in[0];
    const float* w_attn = (const float*)d_in[1];
    const float* w_proj = (const float*)d_in[2];
    float* out = (float*)d_out;

    float* qkv = nullptr;
    float* yb  = nullptr;
    cudaGetSymbolAddress((void**)&qkv, g_qkv);
    cudaGetSymbolAddress((void**)&yb,  g_y);

    const int attn_smem = ATTN_SMEM_FLOATS * (int)sizeof(float);
    cudaFuncSetAttribute(attn_kernel,
                         cudaFuncAttributeMaxDynamicSharedMemorySize, attn_smem);

    // 1) QKV projection: qkv = x @ w_attn^T   [8192,1536]
    {
        dim3 grid(QKVN / GBN, M_TOT / GBM);
        gemm_mma<<<grid, 256>>>(x, w_attn, qkv, M_TOT, QKVN, CC);
    }
    // 2) windowed attention -> y [8192,512]
    {
        dim3 grid(TT / QT, HH, BB);
        attn_kernel<<<grid, 256, attn_smem>>>(qkv, yb);
    }
    // 3) output projection: out = y @ w_proj^T  [8192,512]
    {
        dim3 grid(CC / GBN, M_TOT / GBM);
        gemm_mma<<<grid, 256>>>(yb, w_proj, out, M_TOT, CC, CC);
    }
}

// round 4
// speedup vs baseline: 2.7790x; 1.4724x over previous
#include <cuda_runtime.h>
#include <math.h>
#include <stdint.h>

#define BB   2
#define TT   4096
#define CC   512
#define HH   8
#define DD   64
#define MEMW 256

#define M_TOT (BB*TT)     // 8192
#define QKVN  (3*CC)      // 1536

// scratch (allocation-free contract: device globals)
__device__ float g_qkv[BB*TT*3*CC];   // [B*T, 3C]
__device__ float g_y[BB*TT*CC];       // [B*T, C]

// ===========================================================================
// helpers
// ===========================================================================
__device__ __forceinline__ uint32_t smem_u32(const void* p) {
    uint32_t a;
    asm("{ .reg .u64 t; cvta.to.shared.u64 t, %1; cvt.u32.u64 %0, t; }"
        : "=r"(a) : "l"(p));
    return a;
}
__device__ __forceinline__ uint32_t f2tf32(float f) {
    uint32_t r;
    asm("cvt.rna.tf32.f32 %0, %1;" : "=r"(r) : "f"(f));
    return r;
}
#define SW128(off) ((off) ^ (((off) >> 3) & 0x70))

#define LDSM_X4(r0, r1, r2, r3, addr) \
    asm volatile("ldmatrix.sync.aligned.m8n8.x4.shared.b16 {%0,%1,%2,%3}, [%4];" \
                 : "=r"(r0), "=r"(r1), "=r"(r2), "=r"(r3) : "r"(addr))

#define MMA_TF32(c, a0, a1, a2, a3, b0, b1) \
    asm volatile("mma.sync.aligned.m16n8k8.row.col.f32.tf32.tf32.f32 " \
                 "{%0,%1,%2,%3}, {%4,%5,%6,%7}, {%8,%9}, {%0,%1,%2,%3};" \
                 : "+f"((c)[0]), "+f"((c)[1]), "+f"((c)[2]), "+f"((c)[3]) \
                 : "r"(a0), "r"(a1), "r"(a2), "r"(a3), "r"(b0), "r"(b1))

// ===========================================================================
// tf32 mma.sync GEMM (NT): C[m,n] = sum_k A[m,k] * W[n,k]  (unchanged R3)
// ===========================================================================
#define GBM 128
#define GBN 128
#define GBK 32

__global__ __launch_bounds__(256) void gemm_mma(const float* __restrict__ A,
                                                const float* __restrict__ W,
                                                float* __restrict__ Cout,
                                                int M, int N, int K) {
    __shared__ float smA[GBM * GBK];
    __shared__ float smB[GBN * GBK];

    const int tid  = threadIdx.x;
    const int lane = tid & 31;
    const int wid  = tid >> 5;
    const int wm   = wid & 3;
    const int wn   = wid >> 2;
    const int m0 = blockIdx.y * GBM;
    const int n0 = blockIdx.x * GBN;

    const uint32_t sA = smem_u32(smA);
    const uint32_t sB = smem_u32(smB);

    float acc[2][8][4];
    #pragma unroll
    for (int i = 0; i < 2; i++)
        #pragma unroll
        for (int j = 0; j < 8; j++)
            #pragma unroll
            for (int k = 0; k < 4; k++) acc[i][j][k] = 0.f;

    const int a_row_in = (lane & 15);
    const int a_c16_in = (lane >> 4);
    const int b_row_in = (lane & 7) + ((lane >> 4) << 3);
    const int b_c16_in = ((lane >> 3) & 1);

    const int nk = K / GBK;
    for (int kt = 0; kt < nk; kt++) {
        const int k0 = kt * GBK;
        #pragma unroll
        for (int it = 0; it < 4; it++) {
            int i = tid + it * 256;
            int row = i >> 3;
            int c16 = i & 7;
            float4 v = *(const float4*)&A[(size_t)(m0 + row) * K + k0 + c16 * 4];
            uint32_t byte = SW128((uint32_t)(row * 128 + c16 * 16));
            *(uint4*)((char*)smA + byte) =
                make_uint4(f2tf32(v.x), f2tf32(v.y), f2tf32(v.z), f2tf32(v.w));
        }
        #pragma unroll
        for (int it = 0; it < 4; it++) {
            int i = tid + it * 256;
            int row = i >> 3;
            int c16 = i & 7;
            float4 v = *(const float4*)&W[(size_t)(n0 + row) * K + k0 + c16 * 4];
            uint32_t byte = SW128((uint32_t)(row * 128 + c16 * 16));
            *(uint4*)((char*)smB + byte) =
                make_uint4(f2tf32(v.x), f2tf32(v.y), f2tf32(v.z), f2tf32(v.w));
        }
        __syncthreads();

        #pragma unroll
        for (int ks = 0; ks < 4; ks++) {
            uint32_t a[2][4];
            #pragma unroll
            for (int fm = 0; fm < 2; fm++) {
                int row = wm * 32 + fm * 16 + a_row_in;
                int c16 = ks * 2 + a_c16_in;
                uint32_t addr = sA + SW128((uint32_t)(row * 128 + c16 * 16));
                LDSM_X4(a[fm][0], a[fm][1], a[fm][2], a[fm][3], addr);
            }
            uint32_t b[4][4];
            #pragma unroll
            for (int g = 0; g < 4; g++) {
                int row = wn * 64 + g * 16 + b_row_in;
                int c16 = ks * 2 + b_c16_in;
                uint32_t addr = sB + SW128((uint32_t)(row * 128 + c16 * 16));
                LDSM_X4(b[g][0], b[g][1], b[g][2], b[g][3], addr);
            }
            #pragma unroll
            for (int fm = 0; fm < 2; fm++)
                #pragma unroll
                for (int fn = 0; fn < 8; fn++) {
                    const int bg = fn >> 1;
                    if (fn & 1) {
                        MMA_TF32(acc[fm][fn], a[fm][0], a[fm][1], a[fm][2], a[fm][3],
                                 b[bg][2], b[bg][3]);
                    } else {
                        MMA_TF32(acc[fm][fn], a[fm][0], a[fm][1], a[fm][2], a[fm][3],
                                 b[bg][0], b[bg][1]);
                    }
                }
        }
        __syncthreads();
    }

    const int g = lane >> 2;
    const int cpair = (lane & 3) * 2;
    #pragma unroll
    for (int fm = 0; fm < 2; fm++) {
        #pragma unroll
        for (int fn = 0; fn < 8; fn++) {
            int r = m0 + wm * 32 + fm * 16 + g;
            int c = n0 + wn * 64 + fn * 8 + cpair;
            *(float2*)&Cout[(size_t)r * N + c] =
                make_float2(acc[fm][fn][0], acc[fm][fn][1]);
            *(float2*)&Cout[(size_t)(r + 8) * N + c] =
                make_float2(acc[fm][fn][2], acc[fm][fn][3]);
        }
    }
}

// ===========================================================================
// Sliding-window attention, tf32 mma.sync version.
// One CTA = 64 queries of one (b,h); 5 key tiles of 64.
// Two-pass: QK^T strip -> softmax (stores tf32 P) -> P.V.
// ===========================================================================
#define QT 64
#define KT 64
#define NKT 5
#define NK  (NKT*KT)      // 320
#define SPITCH 324        // floats per S row

// smem floats: Qs 2*2048, KVs 2*2048, S 64*324, red 256, rowsum 64
#define SUBSZ 2048                           // floats per sub-tile [64][32]
#define ATTN_SMEM_FLOATS (2*SUBSZ + 2*SUBSZ + QT*SPITCH + 256 + 64)

__global__ __launch_bounds__(256) void attn_mma(const float* __restrict__ qkv,
                                                float* __restrict__ y) {
    extern __shared__ float sh[];
    float* Qs     = sh;                       // 2 subs [64 rows][32 tf32] SW128
    float* KVs    = Qs + 2 * SUBSZ;           // K (natural) or V^T, 2 subs
    float* S      = KVs + 2 * SUBSZ;          // [64][SPITCH] fp32 -> tf32 bits
    float* red    = S + QT * SPITCH;          // [64][4]
    float* rowsum = red + 256;                // [64]
    uint32_t* Su  = (uint32_t*)S;

    const int tid  = threadIdx.x;
    const int lane = tid & 31;
    const int wid  = tid >> 5;
    const int wm   = wid & 3;                 // 16-row q slice
    const int wn   = wid >> 2;                // 32-col slice (keys / d)
    const int q0 = blockIdx.x * QT;
    const int h  = blockIdx.y;
    const int b  = blockIdx.z;
    const int kstart = q0 - MEMW;

    const float* qbase = qkv + (size_t)b * TT * QKVN + h * DD;
    const float* kbase = qbase + CC;
    const float* vbase = qbase + 2 * CC;

    const uint32_t uQ  = smem_u32(Qs);
    const uint32_t uKV = smem_u32(KVs);

    const int a_row_in = (lane & 15);
    const int a_c16_in = (lane >> 4);
    const int b_row_in = (lane & 7) + ((lane >> 4) << 3);
    const int b_c16_in = ((lane >> 3) & 1);
    const int g  = lane >> 2;
    const int c2 = (lane & 3) * 2;

    // ---- load Q tile (64x64) as tf32, SW128, 2 sub-tiles by d ----
    #pragma unroll
    for (int it = 0; it < 4; it++) {
        int idx = it * 256 + tid;
        int row = idx >> 4;
        int c16 = idx & 15;
        int sub = c16 >> 3;
        int c   = c16 & 7;
        float4 v = *(const float4*)&qbase[(size_t)(q0 + row) * QKVN + c16 * 4];
        uint32_t byte = SW128((uint32_t)(row * 128 + c * 16));
        *(uint4*)((char*)Qs + sub * (SUBSZ * 4) + byte) =
            make_uint4(f2tf32(v.x), f2tf32(v.y), f2tf32(v.z), f2tf32(v.w));
    }

    // ---- score phase ----
    for (int kt = 0; kt < NKT; kt++) {
        __syncthreads();                       // Q ready / prev mma done with KVs
        const int kb = kstart + kt * KT;
        // load K tile (natural [key][d]) as tf32
        #pragma unroll
        for (int it = 0; it < 4; it++) {
            int idx = it * 256 + tid;
            int row = idx >> 4;
            int c16 = idx & 15;
            int sub = c16 >> 3;
            int c   = c16 & 7;
            int gk  = kb + row;
            float4 v = make_float4(0.f, 0.f, 0.f, 0.f);
            if (gk >= 0) v = *(const float4*)&kbase[(size_t)gk * QKVN + c16 * 4];
            uint32_t byte = SW128((uint32_t)(row * 128 + c * 16));
            *(uint4*)((char*)KVs + sub * (SUBSZ * 4) + byte) =
                make_uint4(f2tf32(v.x), f2tf32(v.y), f2tf32(v.z), f2tf32(v.w));
        }
        __syncthreads();

        float acc[4][4];
        #pragma unroll
        for (int i = 0; i < 4; i++)
            #pragma unroll
            for (int j = 0; j < 4; j++) acc[i][j] = 0.f;

        #pragma unroll
        for (int ks = 0; ks < 8; ks++) {
            const int sub = ks >> 2;
            const int cc  = (ks & 3) * 2;
            uint32_t a[4];
            {
                int row = wm * 16 + a_row_in;
                int c16 = cc + a_c16_in;
                uint32_t addr = uQ + sub * (SUBSZ * 4)
                              + SW128((uint32_t)(row * 128 + c16 * 16));
                LDSM_X4(a[0], a[1], a[2], a[3], addr);
            }
            uint32_t bf[2][4];
            #pragma unroll
            for (int g2 = 0; g2 < 2; g2++) {
                int row = wn * 32 + g2 * 16 + b_row_in;
                int c16 = cc + b_c16_in;
                uint32_t addr = uKV + sub * (SUBSZ * 4)
                              + SW128((uint32_t)(row * 128 + c16 * 16));
                LDSM_X4(bf[g2][0], bf[g2][1], bf[g2][2], bf[g2][3], addr);
            }
            #pragma unroll
            for (int fn = 0; fn < 4; fn++) {
                const int bg = fn >> 1;
                if (fn & 1) {
                    MMA_TF32(acc[fn], a[0], a[1], a[2], a[3], bf[bg][2], bf[bg][3]);
                } else {
                    MMA_TF32(acc[fn], a[0], a[1], a[2], a[3], bf[bg][0], bf[bg][1]);
                }
            }
        }

        // masked, scaled store into S strip
        const int qi0 = q0 + wm * 16 + g;
        const int qi1 = qi0 + 8;
        #pragma unroll
        for (int fn = 0; fn < 4; fn++) {
            int c  = wn * 32 + fn * 8 + c2;    // tile-local col
            int kj = kb + c;
            #pragma unroll
            for (int jj = 0; jj < 2; jj++) {
                int k = kj + jj;
                bool ok0 = (k >= 0) && (k <= qi0) && (qi0 - k <= MEMW);
                bool ok1 = (k >= 0) && (k <= qi1) && (qi1 - k <= MEMW);
                S[(wm * 16 + g) * SPITCH + kt * KT + c + jj] =
                    ok0 ? acc[fn][jj] * 0.125f : -1e30f;
                S[(wm * 16 + g + 8) * SPITCH + kt * KT + c + jj] =
                    ok1 ? acc[fn][2 + jj] * 0.125f : -1e30f;
            }
        }
    }
    __syncthreads();

    // ---- softmax: 4 threads/row; write back tf32 bits ----
    {
        int r = tid >> 2;
        int s = tid & 3;
        float mx = -1e30f;
        for (int c = s; c < NK; c += 4) mx = fmaxf(mx, S[r * SPITCH + c]);
        red[r * 4 + s] = mx;
        __syncthreads();
        mx = fmaxf(fmaxf(red[r * 4 + 0], red[r * 4 + 1]),
                   fmaxf(red[r * 4 + 2], red[r * 4 + 3]));
        __syncthreads();
        float sum = 0.f;
        for (int c = s; c < NK; c += 4) {
            float e = __expf(S[r * SPITCH + c] - mx);
            Su[r * SPITCH + c] = f2tf32(e);
            sum += e;
        }
        red[r * 4 + s] = sum;
        __syncthreads();
        if (s == 0)
            rowsum[r] = red[r * 4 + 0] + red[r * 4 + 1] +
                        red[r * 4 + 2] + red[r * 4 + 3];
    }

    // ---- PV phase: O += P_tile (64xKT) x V_tile (KTx64) ----
    float oacc[4][4];
    #pragma unroll
    for (int i = 0; i < 4; i++)
        #pragma unroll
        for (int j = 0; j < 4; j++) oacc[i][j] = 0.f;

    for (int kt = 0; kt < NKT; kt++) {
        __syncthreads();                        // softmax done / prev mma done
        const int kb = kstart + kt * KT;
        // load V tile transposed: Vt[d][key], 2 subs by key half.
        // lane mapping chosen for conflict-free transposed stores.
        #pragma unroll
        for (int it = 0; it < 4; it++) {
            int idx = it * 256 + tid;
            int kk = (idx & 15) + 16 * (idx >> 8);   // idx>>8 == it
            int d4 = (idx >> 4) & 15;
            int gk = kb + kk;
            float4 v = make_float4(0.f, 0.f, 0.f, 0.f);
            if (gk >= 0) v = *(const float4*)&vbase[(size_t)gk * QKVN + d4 * 4];
            uint32_t vb[4] = {f2tf32(v.x), f2tf32(v.y), f2tf32(v.z), f2tf32(v.w)};
            int sub = kk >> 5;
            int k5  = kk & 31;
            #pragma unroll
            for (int j = 0; j < 4; j++) {
                uint32_t byte = SW128((uint32_t)((d4 * 4 + j) * 128 + k5 * 4));
                *(uint32_t*)((char*)KVs + sub * (SUBSZ * 4) + byte) = vb[j];
            }
        }
        __syncthreads();

        #pragma unroll
        for (int ks = 0; ks < 8; ks++) {
            const int key0 = kt * KT + ks * 8;
            const int sub  = ks >> 2;
            const int cc   = (ks & 3) * 2;
            // A = P fragment via 4 scalar LDS (tf32 bits already in S)
            uint32_t a[4];
            {
                int r0 = wm * 16 + g;
                int kx = key0 + (lane & 3);
                a[0] = Su[r0 * SPITCH + kx];
                a[1] = Su[(r0 + 8) * SPITCH + kx];
                a[2] = Su[r0 * SPITCH + kx + 4];
                a[3] = Su[(r0 + 8) * SPITCH + kx + 4];
            }
            uint32_t bf[2][4];
            #pragma unroll
            for (int g2 = 0; g2 < 2; g2++) {
                int row = wn * 32 + g2 * 16 + b_row_in;   // row = d
                int c16 = cc + b_c16_in;                  // key within sub
                uint32_t addr = uKV + sub * (SUBSZ * 4)
                              + SW128((uint32_t)(row * 128 + c16 * 16));
                LDSM_X4(bf[g2][0], bf[g2][1], bf[g2][2], bf[g2][3], addr);
            }
            #pragma unroll
            for (int fn = 0; fn < 4; fn++) {
                const int bg = fn >> 1;
                if (fn & 1) {
                    MMA_TF32(oacc[fn], a[0], a[1], a[2], a[3], bf[bg][2], bf[bg][3]);
                } else {
                    MMA_TF32(oacc[fn], a[0], a[1], a[2], a[3], bf[bg][0], bf[bg][1]);
                }
            }
        }
    }
    __syncthreads();

    // ---- epilogue: normalize, write y[b, q, h*64 + d] ----
    {
        int r0 = wm * 16 + g;
        float inv0 = 1.0f / rowsum[r0];
        float inv1 = 1.0f / rowsum[r0 + 8];
        #pragma unroll
        for (int fn = 0; fn < 4; fn++) {
            int col = wn * 32 + fn * 8 + c2;
            float* p0 = &y[(size_t)(b * TT + q0 + r0) * CC + h * DD + col];
            float* p1 = &y[(size_t)(b * TT + q0 + r0 + 8) * CC + h * DD + col];
            *(float2*)p0 = make_float2(oacc[fn][0] * inv0, oacc[fn][1] * inv0);
            *(float2*)p1 = make_float2(oacc[fn][2] * inv1, oacc[fn][3] * inv1);
        }
    }
}

// ===========================================================================
extern "C" void kernel_launch(void* const* d_in, const int* in_sizes, int n_in,
                              void* d_out, int out_size) {
    const float* x      = (const float*)d_in[0];
    const float* w_attn = (const float*)d_in[1];
    const float* w_proj = (const float*)d_in[2];
    float* out = (float*)d_out;

    float* qkv = nullptr;
    float* yb  = nullptr;
    cudaGetSymbolAddress((void**)&qkv, g_qkv);
    cudaGetSymbolAddress((void**)&yb,  g_y);

    const int attn_smem = ATTN_SMEM_FLOATS * (int)sizeof(float);
    cudaFuncSetAttribute(attn_mma,
                         cudaFuncAttributeMaxDynamicSharedMemorySize, attn_smem);

    // 1) QKV projection: qkv = x @ w_attn^T   [8192,1536]
    {
        dim3 grid(QKVN / GBN, M_TOT / GBM);
        gemm_mma<<<grid, 256>>>(x, w_attn, qkv, M_TOT, QKVN, CC);
    }
    // 2) windowed attention -> y [8192,512]
    {
        dim3 grid(TT / QT, HH, BB);
        attn_mma<<<grid, 256, attn_smem>>>(qkv, yb);
    }
    // 3) output projection: out = y @ w_proj^T  [8192,512]
    {
        dim3 grid(CC / GBN, M_TOT / GBM);
        gemm_mma<<<grid, 256>>>(yb, w_proj, out, M_TOT, CC, CC);
    }
}

// round 5
// speedup vs baseline: 3.2958x; 1.1860x over previous
#include <cuda_runtime.h>
#include <math.h>
#include <stdint.h>

#define BB   2
#define TT   4096
#define CC   512
#define HH   8
#define DD   64
#define MEMW 256

#define M_TOT (BB*TT)     // 8192
#define QKVN  (3*CC)      // 1536

#define XN  (M_TOT*CC)        // 4194304
#define WAN (QKVN*CC)         // 786432
#define WPN (CC*CC)           // 262144

// scratch (allocation-free contract: device globals)
__device__ float g_qkv[BB*TT*3*CC];   // [B*T, 3C]
__device__ float g_y[BB*TT*CC];       // [B*T, C]  (tf32-rounded values)
__device__ float g_xc[XN];            // tf32-rounded x
__device__ float g_wac[WAN];          // tf32-rounded w_attn
__device__ float g_wpc[WPN];          // tf32-rounded w_proj

// ===========================================================================
// helpers
// ===========================================================================
__device__ __forceinline__ uint32_t smem_u32(const void* p) {
    uint32_t a;
    asm("{ .reg .u64 t; cvta.to.shared.u64 t, %1; cvt.u32.u64 %0, t; }"
        : "=r"(a) : "l"(p));
    return a;
}
__device__ __forceinline__ uint32_t f2tf32(float f) {
    uint32_t r;
    asm("cvt.rna.tf32.f32 %0, %1;" : "=r"(r) : "f"(f));
    return r;
}
#define SW128(off) ((off) ^ (((off) >> 3) & 0x70))

#define LDSM_X4(r0, r1, r2, r3, addr) \
    asm volatile("ldmatrix.sync.aligned.m8n8.x4.shared.b16 {%0,%1,%2,%3}, [%4];" \
                 : "=r"(r0), "=r"(r1), "=r"(r2), "=r"(r3) : "r"(addr))

#define MMA_TF32(c, a0, a1, a2, a3, b0, b1) \
    asm volatile("mma.sync.aligned.m16n8k8.row.col.f32.tf32.tf32.f32 " \
                 "{%0,%1,%2,%3}, {%4,%5,%6,%7}, {%8,%9}, {%0,%1,%2,%3};" \
                 : "+f"((c)[0]), "+f"((c)[1]), "+f"((c)[2]), "+f"((c)[3]) \
                 : "r"(a0), "r"(a1), "r"(a2), "r"(a3), "r"(b0), "r"(b1))

__device__ __forceinline__ void cp_async16(uint32_t s, const void* g) {
    asm volatile("cp.async.cg.shared.global [%0], [%1], 16;"
                 :: "r"(s), "l"(__cvta_generic_to_global(g)));
}
#define CP_COMMIT() asm volatile("cp.async.commit_group;" ::: "memory")
#define CP_WAIT(n)  asm volatile("cp.async.wait_group %0;" :: "n"(n) : "memory")

// ===========================================================================
// pre-convert: tf32-round x, w_attn, w_proj into device globals (float4-wide)
// ===========================================================================
__global__ __launch_bounds__(256) void convert_kernel(const float* __restrict__ x,
                                                      const float* __restrict__ wa,
                                                      const float* __restrict__ wp) {
    const int i4 = blockIdx.x * 256 + threadIdx.x;       // float4 index
    const int total4 = (XN + WAN + WPN) / 4;
    if (i4 >= total4) return;
    const float* src;
    float* dst;
    int j4 = i4;
    if (j4 < XN / 4)                  { src = x;  dst = g_xc; }
    else if ((j4 -= XN / 4) < WAN / 4){ src = wa; dst = g_wac; }
    else                              { j4 -= WAN / 4; src = wp; dst = g_wpc; }
    float4 v = *(const float4*)&src[j4 * 4];
    uint4 o = make_uint4(f2tf32(v.x), f2tf32(v.y), f2tf32(v.z), f2tf32(v.w));
    *(uint4*)&dst[j4 * 4] = o;
}

// ===========================================================================
// tf32 mma.sync GEMM (NT), cp.async 3-stage pipeline.
// Inputs must be pre-converted to tf32 values.
// CTA tile 128x128, BK=32, 8 warps (4m x 2n).
// ===========================================================================
#define GBM 128
#define GBN 128
#define GBK 32
#define STAGES 3
#define TILE_B (GBM * GBK * 4)          // 16384 bytes per A or B tile
#define STAGE_B (2 * TILE_B)            // 32768
#define GEMM_SMEM (STAGES * STAGE_B)    // 98304

__global__ __launch_bounds__(256) void gemm_ca(const float* __restrict__ A,
                                               const float* __restrict__ W,
                                               float* __restrict__ Cout,
                                               int M, int N, int K) {
    extern __shared__ char dynsm[];
    const uint32_t smb = smem_u32(dynsm);

    const int tid  = threadIdx.x;
    const int lane = tid & 31;
    const int wid  = tid >> 5;
    const int wm   = wid & 3;
    const int wn   = wid >> 2;
    const int m0 = blockIdx.y * GBM;
    const int n0 = blockIdx.x * GBN;

    // copy geometry: 1024 16B chunks per tile; 4 chunks/thread/tile
    const int crow = tid >> 3;           // 0..31 base row (x4 iters -> 128)
    const int cc16 = tid & 7;
    const uint32_t cbyte = SW128((uint32_t)(crow * 128 + cc16 * 16));

    const int nk = K / GBK;

    auto issue_copy = [&](int kt) {
        const int s = kt % STAGES;
        const int k0 = kt * GBK;
        const uint32_t sa = smb + s * STAGE_B;
        const uint32_t sb = sa + TILE_B;
        #pragma unroll
        for (int it = 0; it < 4; it++) {
            const int row = crow + it * 32;
            cp_async16(sa + cbyte + it * 32 * 128,
                       &A[(size_t)(m0 + row) * K + k0 + cc16 * 4]);
        }
        #pragma unroll
        for (int it = 0; it < 4; it++) {
            const int row = crow + it * 32;
            cp_async16(sb + cbyte + it * 32 * 128,
                       &W[(size_t)(n0 + row) * K + k0 + cc16 * 4]);
        }
    };

    float acc[2][8][4];
    #pragma unroll
    for (int i = 0; i < 2; i++)
        #pragma unroll
        for (int j = 0; j < 8; j++)
            #pragma unroll
            for (int k = 0; k < 4; k++) acc[i][j][k] = 0.f;

    const int a_row_in = (lane & 15);
    const int a_c16_in = (lane >> 4);
    const int b_row_in = (lane & 7) + ((lane >> 4) << 3);
    const int b_c16_in = ((lane >> 3) & 1);

    // prologue: fill STAGES-1 stages
    #pragma unroll
    for (int s = 0; s < STAGES - 1; s++) {
        issue_copy(s);
        CP_COMMIT();
    }

    for (int kt = 0; kt < nk; kt++) {
        CP_WAIT(STAGES - 2);
        __syncthreads();

        // issue next stage copy (overwrites buffer read at kt-1; all warps
        // are past that mma because they passed this iteration's barrier)
        if (kt + STAGES - 1 < nk) issue_copy(kt + STAGES - 1);
        CP_COMMIT();

        const uint32_t sa = smb + (kt % STAGES) * STAGE_B;
        const uint32_t sb = sa + TILE_B;

        #pragma unroll
        for (int ks = 0; ks < 4; ks++) {
            uint32_t a[2][4];
            #pragma unroll
            for (int fm = 0; fm < 2; fm++) {
                int row = wm * 32 + fm * 16 + a_row_in;
                int c16 = ks * 2 + a_c16_in;
                LDSM_X4(a[fm][0], a[fm][1], a[fm][2], a[fm][3],
                        sa + SW128((uint32_t)(row * 128 + c16 * 16)));
            }
            uint32_t b[4][4];
            #pragma unroll
            for (int g = 0; g < 4; g++) {
                int row = wn * 64 + g * 16 + b_row_in;
                int c16 = ks * 2 + b_c16_in;
                LDSM_X4(b[g][0], b[g][1], b[g][2], b[g][3],
                        sb + SW128((uint32_t)(row * 128 + c16 * 16)));
            }
            #pragma unroll
            for (int fm = 0; fm < 2; fm++)
                #pragma unroll
                for (int fn = 0; fn < 8; fn++) {
                    const int bg = fn >> 1;
                    if (fn & 1) {
                        MMA_TF32(acc[fm][fn], a[fm][0], a[fm][1], a[fm][2], a[fm][3],
                                 b[bg][2], b[bg][3]);
                    } else {
                        MMA_TF32(acc[fm][fn], a[fm][0], a[fm][1], a[fm][2], a[fm][3],
                                 b[bg][0], b[bg][1]);
                    }
                }
        }
        __syncthreads();
    }

    const int g = lane >> 2;
    const int cpair = (lane & 3) * 2;
    #pragma unroll
    for (int fm = 0; fm < 2; fm++) {
        #pragma unroll
        for (int fn = 0; fn < 8; fn++) {
            int r = m0 + wm * 32 + fm * 16 + g;
            int c = n0 + wn * 64 + fn * 8 + cpair;
            *(float2*)&Cout[(size_t)r * N + c] =
                make_float2(acc[fm][fn][0], acc[fm][fn][1]);
            *(float2*)&Cout[(size_t)(r + 8) * N + c] =
                make_float2(acc[fm][fn][2], acc[fm][fn][3]);
        }
    }
}

// ===========================================================================
// Sliding-window attention, tf32 mma.sync (R4 version; epilogue emits tf32)
// ===========================================================================
#define QT 64
#define KT 64
#define NKT 5
#define NK  (NKT*KT)      // 320
#define SPITCH 324

#define SUBSZ 2048
#define ATTN_SMEM_FLOATS (2*SUBSZ + 2*SUBSZ + QT*SPITCH + 256 + 64)

__global__ __launch_bounds__(256) void attn_mma(const float* __restrict__ qkv,
                                                float* __restrict__ y) {
    extern __shared__ float sh[];
    float* Qs     = sh;
    float* KVs    = Qs + 2 * SUBSZ;
    float* S      = KVs + 2 * SUBSZ;
    float* red    = S + QT * SPITCH;
    float* rowsum = red + 256;
    uint32_t* Su  = (uint32_t*)S;

    const int tid  = threadIdx.x;
    const int lane = tid & 31;
    const int wid  = tid >> 5;
    const int wm   = wid & 3;
    const int wn   = wid >> 2;
    const int q0 = blockIdx.x * QT;
    const int h  = blockIdx.y;
    const int b  = blockIdx.z;
    const int kstart = q0 - MEMW;

    const float* qbase = qkv + (size_t)b * TT * QKVN + h * DD;
    const float* kbase = qbase + CC;
    const float* vbase = qbase + 2 * CC;

    const uint32_t uQ  = smem_u32(Qs);
    const uint32_t uKV = smem_u32(KVs);

    const int a_row_in = (lane & 15);
    const int a_c16_in = (lane >> 4);
    const int b_row_in = (lane & 7) + ((lane >> 4) << 3);
    const int b_c16_in = ((lane >> 3) & 1);
    const int g  = lane >> 2;
    const int c2 = (lane & 3) * 2;

    #pragma unroll
    for (int it = 0; it < 4; it++) {
        int idx = it * 256 + tid;
        int row = idx >> 4;
        int c16 = idx & 15;
        int sub = c16 >> 3;
        int c   = c16 & 7;
        float4 v = *(const float4*)&qbase[(size_t)(q0 + row) * QKVN + c16 * 4];
        uint32_t byte = SW128((uint32_t)(row * 128 + c * 16));
        *(uint4*)((char*)Qs + sub * (SUBSZ * 4) + byte) =
            make_uint4(f2tf32(v.x), f2tf32(v.y), f2tf32(v.z), f2tf32(v.w));
    }

    for (int kt = 0; kt < NKT; kt++) {
        __syncthreads();
        const int kb = kstart + kt * KT;
        #pragma unroll
        for (int it = 0; it < 4; it++) {
            int idx = it * 256 + tid;
            int row = idx >> 4;
            int c16 = idx & 15;
            int sub = c16 >> 3;
            int c   = c16 & 7;
            int gk  = kb + row;
            float4 v = make_float4(0.f, 0.f, 0.f, 0.f);
            if (gk >= 0) v = *(const float4*)&kbase[(size_t)gk * QKVN + c16 * 4];
            uint32_t byte = SW128((uint32_t)(row * 128 + c * 16));
            *(uint4*)((char*)KVs + sub * (SUBSZ * 4) + byte) =
                make_uint4(f2tf32(v.x), f2tf32(v.y), f2tf32(v.z), f2tf32(v.w));
        }
        __syncthreads();

        float acc[4][4];
        #pragma unroll
        for (int i = 0; i < 4; i++)
            #pragma unroll
            for (int j = 0; j < 4; j++) acc[i][j] = 0.f;

        #pragma unroll
        for (int ks = 0; ks < 8; ks++) {
            const int sub = ks >> 2;
            const int cc  = (ks & 3) * 2;
            uint32_t a[4];
            {
                int row = wm * 16 + a_row_in;
                int c16 = cc + a_c16_in;
                LDSM_X4(a[0], a[1], a[2], a[3],
                        uQ + sub * (SUBSZ * 4) + SW128((uint32_t)(row * 128 + c16 * 16)));
            }
            uint32_t bf[2][4];
            #pragma unroll
            for (int g2 = 0; g2 < 2; g2++) {
                int row = wn * 32 + g2 * 16 + b_row_in;
                int c16 = cc + b_c16_in;
                LDSM_X4(bf[g2][0], bf[g2][1], bf[g2][2], bf[g2][3],
                        uKV + sub * (SUBSZ * 4) + SW128((uint32_t)(row * 128 + c16 * 16)));
            }
            #pragma unroll
            for (int fn = 0; fn < 4; fn++) {
                const int bg = fn >> 1;
                if (fn & 1) {
                    MMA_TF32(acc[fn], a[0], a[1], a[2], a[3], bf[bg][2], bf[bg][3]);
                } else {
                    MMA_TF32(acc[fn], a[0], a[1], a[2], a[3], bf[bg][0], bf[bg][1]);
                }
            }
        }

        const int qi0 = q0 + wm * 16 + g;
        const int qi1 = qi0 + 8;
        #pragma unroll
        for (int fn = 0; fn < 4; fn++) {
            int c  = wn * 32 + fn * 8 + c2;
            int kj = kb + c;
            #pragma unroll
            for (int jj = 0; jj < 2; jj++) {
                int k = kj + jj;
                bool ok0 = (k >= 0) && (k <= qi0) && (qi0 - k <= MEMW);
                bool ok1 = (k >= 0) && (k <= qi1) && (qi1 - k <= MEMW);
                S[(wm * 16 + g) * SPITCH + kt * KT + c + jj] =
                    ok0 ? acc[fn][jj] * 0.125f : -1e30f;
                S[(wm * 16 + g + 8) * SPITCH + kt * KT + c + jj] =
                    ok1 ? acc[fn][2 + jj] * 0.125f : -1e30f;
            }
        }
    }
    __syncthreads();

    {
        int r = tid >> 2;
        int s = tid & 3;
        float mx = -1e30f;
        for (int c = s; c < NK; c += 4) mx = fmaxf(mx, S[r * SPITCH + c]);
        red[r * 4 + s] = mx;
        __syncthreads();
        mx = fmaxf(fmaxf(red[r * 4 + 0], red[r * 4 + 1]),
                   fmaxf(red[r * 4 + 2], red[r * 4 + 3]));
        __syncthreads();
        float sum = 0.f;
        for (int c = s; c < NK; c += 4) {
            float e = __expf(S[r * SPITCH + c] - mx);
            Su[r * SPITCH + c] = f2tf32(e);
            sum += e;
        }
        red[r * 4 + s] = sum;
        __syncthreads();
        if (s == 0)
            rowsum[r] = red[r * 4 + 0] + red[r * 4 + 1] +
                        red[r * 4 + 2] + red[r * 4 + 3];
    }

    float oacc[4][4];
    #pragma unroll
    for (int i = 0; i < 4; i++)
        #pragma unroll
        for (int j = 0; j < 4; j++) oacc[i][j] = 0.f;

    for (int kt = 0; kt < NKT; kt++) {
        __syncthreads();
        const int kb = kstart + kt * KT;
        #pragma unroll
        for (int it = 0; it < 4; it++) {
            int idx = it * 256 + tid;
            int kk = (idx & 15) + 16 * (idx >> 8);
            int d4 = (idx >> 4) & 15;
            int gk = kb + kk;
            float4 v = make_float4(0.f, 0.f, 0.f, 0.f);
            if (gk >= 0) v = *(const float4*)&vbase[(size_t)gk * QKVN + d4 * 4];
            uint32_t vb[4] = {f2tf32(v.x), f2tf32(v.y), f2tf32(v.z), f2tf32(v.w)};
            int sub = kk >> 5;
            int k5  = kk & 31;
            #pragma unroll
            for (int j = 0; j < 4; j++) {
                uint32_t byte = SW128((uint32_t)((d4 * 4 + j) * 128 + k5 * 4));
                *(uint32_t*)((char*)KVs + sub * (SUBSZ * 4) + byte) = vb[j];
            }
        }
        __syncthreads();

        #pragma unroll
        for (int ks = 0; ks < 8; ks++) {
            const int key0 = kt * KT + ks * 8;
            const int sub  = ks >> 2;
            const int cc   = (ks & 3) * 2;
            uint32_t a[4];
            {
                int r0 = wm * 16 + g;
                int kx = key0 + (lane & 3);
                a[0] = Su[r0 * SPITCH + kx];
                a[1] = Su[(r0 + 8) * SPITCH + kx];
                a[2] = Su[r0 * SPITCH + kx + 4];
                a[3] = Su[(r0 + 8) * SPITCH + kx + 4];
            }
            uint32_t bf[2][4];
            #pragma unroll
            for (int g2 = 0; g2 < 2; g2++) {
                int row = wn * 32 + g2 * 16 + b_row_in;
                int c16 = cc + b_c16_in;
                LDSM_X4(bf[g2][0], bf[g2][1], bf[g2][2], bf[g2][3],
                        uKV + sub * (SUBSZ * 4) + SW128((uint32_t)(row * 128 + c16 * 16)));
            }
            #pragma unroll
            for (int fn = 0; fn < 4; fn++) {
                const int bg = fn >> 1;
                if (fn & 1) {
                    MMA_TF32(oacc[fn], a[0], a[1], a[2], a[3], bf[bg][2], bf[bg][3]);
                } else {
                    MMA_TF32(oacc[fn], a[0], a[1], a[2], a[3], bf[bg][0], bf[bg][1]);
                }
            }
        }
    }
    __syncthreads();

    // epilogue: normalize, tf32-round (proj gemm reads pre-converted), store
    {
        int r0 = wm * 16 + g;
        float inv0 = 1.0f / rowsum[r0];
        float inv1 = 1.0f / rowsum[r0 + 8];
        #pragma unroll
        for (int fn = 0; fn < 4; fn++) {
            int col = wn * 32 + fn * 8 + c2;
            float* p0 = &y[(size_t)(b * TT + q0 + r0) * CC + h * DD + col];
            float* p1 = &y[(size_t)(b * TT + q0 + r0 + 8) * CC + h * DD + col];
            *(uint2*)p0 = make_uint2(f2tf32(oacc[fn][0] * inv0),
                                     f2tf32(oacc[fn][1] * inv0));
            *(uint2*)p1 = make_uint2(f2tf32(oacc[fn][2] * inv1),
                                     f2tf32(oacc[fn][3] * inv1));
        }
    }
}

// ===========================================================================
extern "C" void kernel_launch(void* const* d_in, const int* in_sizes, int n_in,
                              void* d_out, int out_size) {
    const float* x      = (const float*)d_in[0];
    const float* w_attn = (const float*)d_in[1];
    const float* w_proj = (const float*)d_in[2];
    float* out = (float*)d_out;

    float *qkv = nullptr, *yb = nullptr, *xc = nullptr, *wac = nullptr, *wpc = nullptr;
    cudaGetSymbolAddress((void**)&qkv, g_qkv);
    cudaGetSymbolAddress((void**)&yb,  g_y);
    cudaGetSymbolAddress((void**)&xc,  g_xc);
    cudaGetSymbolAddress((void**)&wac, g_wac);
    cudaGetSymbolAddress((void**)&wpc, g_wpc);

    const int attn_smem = ATTN_SMEM_FLOATS * (int)sizeof(float);
    cudaFuncSetAttribute(attn_mma,
                         cudaFuncAttributeMaxDynamicSharedMemorySize, attn_smem);
    cudaFuncSetAttribute(gemm_ca,
                         cudaFuncAttributeMaxDynamicSharedMemorySize, GEMM_SMEM);

    // 0) tf32 pre-convert of x, w_attn, w_proj
    {
        int total4 = (XN + WAN + WPN) / 4;
        convert_kernel<<<(total4 + 255) / 256, 256>>>(x, w_attn, w_proj);
    }
    // 1) QKV projection: qkv = xc @ wac^T   [8192,1536]
    {
        dim3 grid(QKVN / GBN, M_TOT / GBM);
        gemm_ca<<<grid, 256, GEMM_SMEM>>>(xc, wac, qkv, M_TOT, QKVN, CC);
    }
    // 2) windowed attention -> y [8192,512] (tf32-rounded)
    {
        dim3 grid(TT / QT, HH, BB);
        attn_mma<<<grid, 256, attn_smem>>>(qkv, yb);
    }
    // 3) output projection: out = y @ wpc^T  [8192,512]
    {
        dim3 grid(CC / GBN, M_TOT / GBM);
        gemm_ca<<<grid, 256, GEMM_SMEM>>>(yb, wpc, out, M_TOT, CC, CC);
    }
}

// round 6
// speedup vs baseline: 3.5112x; 1.0653x over previous
#include <cuda_runtime.h>
#include <math.h>
#include <stdint.h>

#define BB   2
#define TT   4096
#define CC   512
#define HH   8
#define DD   64
#define MEMW 256

#define M_TOT (BB*TT)     // 8192
#define QKVN  (3*CC)      // 1536

#define XN  (M_TOT*CC)
#define WAN (QKVN*CC)
#define WPN (CC*CC)

// scratch (allocation-free contract: device globals)
__device__ float g_qkv[BB*TT*3*CC];   // [B*T, 3C] tf32-rounded values
__device__ float g_y[BB*TT*CC];       // [B*T, C]  tf32-rounded values
__device__ float g_xc[XN];            // tf32-rounded x
__device__ float g_wac[WAN];          // tf32-rounded w_attn
__device__ float g_wpc[WPN];          // tf32-rounded w_proj

// ===========================================================================
// helpers
// ===========================================================================
__device__ __forceinline__ uint32_t smem_u32(const void* p) {
    uint32_t a;
    asm("{ .reg .u64 t; cvta.to.shared.u64 t, %1; cvt.u32.u64 %0, t; }"
        : "=r"(a) : "l"(p));
    return a;
}
__device__ __forceinline__ uint32_t f2tf32(float f) {
    uint32_t r;
    asm("cvt.rna.tf32.f32 %0, %1;" : "=r"(r) : "f"(f));
    return r;
}
#define SW128(off) ((off) ^ (((off) >> 3) & 0x70))

#define LDSM_X4(r0, r1, r2, r3, addr) \
    asm volatile("ldmatrix.sync.aligned.m8n8.x4.shared.b16 {%0,%1,%2,%3}, [%4];" \
                 : "=r"(r0), "=r"(r1), "=r"(r2), "=r"(r3) : "r"(addr))

#define MMA_TF32(c, a0, a1, a2, a3, b0, b1) \
    asm volatile("mma.sync.aligned.m16n8k8.row.col.f32.tf32.tf32.f32 " \
                 "{%0,%1,%2,%3}, {%4,%5,%6,%7}, {%8,%9}, {%0,%1,%2,%3};" \
                 : "+f"((c)[0]), "+f"((c)[1]), "+f"((c)[2]), "+f"((c)[3]) \
                 : "r"(a0), "r"(a1), "r"(a2), "r"(a3), "r"(b0), "r"(b1))

__device__ __forceinline__ void cp_async16(uint32_t s, const void* g) {
    asm volatile("cp.async.cg.shared.global [%0], [%1], 16;"
                 :: "r"(s), "l"(__cvta_generic_to_global(g)));
}
__device__ __forceinline__ void cp_async16_z(uint32_t s, const void* g, int sz) {
    asm volatile("cp.async.cg.shared.global [%0], [%1], 16, %2;"
                 :: "r"(s), "l"(__cvta_generic_to_global(g)), "r"(sz));
}
#define CP_COMMIT() asm volatile("cp.async.commit_group;" ::: "memory")
#define CP_WAIT(n)  asm volatile("cp.async.wait_group %0;" :: "n"(n) : "memory")

// ===========================================================================
// pre-convert: tf32-round x, w_attn, w_proj
// ===========================================================================
__global__ __launch_bounds__(256) void convert_kernel(const float* __restrict__ x,
                                                      const float* __restrict__ wa,
                                                      const float* __restrict__ wp) {
    const int i4 = blockIdx.x * 256 + threadIdx.x;
    const int total4 = (XN + WAN + WPN) / 4;
    if (i4 >= total4) return;
    const float* src;
    float* dst;
    int j4 = i4;
    if (j4 < XN / 4)                  { src = x;  dst = g_xc; }
    else if ((j4 -= XN / 4) < WAN / 4){ src = wa; dst = g_wac; }
    else                              { j4 -= WAN / 4; src = wp; dst = g_wpc; }
    float4 v = *(const float4*)&src[j4 * 4];
    uint4 o = make_uint4(f2tf32(v.x), f2tf32(v.y), f2tf32(v.z), f2tf32(v.w));
    *(uint4*)&dst[j4 * 4] = o;
}

// ===========================================================================
// tf32 mma.sync GEMM (NT), cp.async 3-stage pipeline.
// round_out!=0 -> output values rounded to tf32 (bit-exact with converting
// them at the consumer's load, which is what previous rounds did).
// ===========================================================================
#define GBM 128
#define GBN 128
#define GBK 32
#define STAGES 3
#define TILE_B (GBM * GBK * 4)
#define STAGE_B (2 * TILE_B)
#define GEMM_SMEM (STAGES * STAGE_B)

__global__ __launch_bounds__(256) void gemm_ca(const float* __restrict__ A,
                                               const float* __restrict__ W,
                                               float* __restrict__ Cout,
                                               int M, int N, int K, int round_out) {
    extern __shared__ char dynsm[];
    const uint32_t smb = smem_u32(dynsm);

    const int tid  = threadIdx.x;
    const int lane = tid & 31;
    const int wid  = tid >> 5;
    const int wm   = wid & 3;
    const int wn   = wid >> 2;
    const int m0 = blockIdx.y * GBM;
    const int n0 = blockIdx.x * GBN;

    const int crow = tid >> 3;
    const int cc16 = tid & 7;
    const uint32_t cbyte = SW128((uint32_t)(crow * 128 + cc16 * 16));

    const int nk = K / GBK;

    auto issue_copy = [&](int kt) {
        const int s = kt % STAGES;
        const int k0 = kt * GBK;
        const uint32_t sa = smb + s * STAGE_B;
        const uint32_t sb = sa + TILE_B;
        #pragma unroll
        for (int it = 0; it < 4; it++) {
            const int row = crow + it * 32;
            cp_async16(sa + cbyte + it * 32 * 128,
                       &A[(size_t)(m0 + row) * K + k0 + cc16 * 4]);
        }
        #pragma unroll
        for (int it = 0; it < 4; it++) {
            const int row = crow + it * 32;
            cp_async16(sb + cbyte + it * 32 * 128,
                       &W[(size_t)(n0 + row) * K + k0 + cc16 * 4]);
        }
    };

    float acc[2][8][4];
    #pragma unroll
    for (int i = 0; i < 2; i++)
        #pragma unroll
        for (int j = 0; j < 8; j++)
            #pragma unroll
            for (int k = 0; k < 4; k++) acc[i][j][k] = 0.f;

    const int a_row_in = (lane & 15);
    const int a_c16_in = (lane >> 4);
    const int b_row_in = (lane & 7) + ((lane >> 4) << 3);
    const int b_c16_in = ((lane >> 3) & 1);

    #pragma unroll
    for (int s = 0; s < STAGES - 1; s++) {
        issue_copy(s);
        CP_COMMIT();
    }

    for (int kt = 0; kt < nk; kt++) {
        CP_WAIT(STAGES - 2);
        __syncthreads();

        if (kt + STAGES - 1 < nk) issue_copy(kt + STAGES - 1);
        CP_COMMIT();

        const uint32_t sa = smb + (kt % STAGES) * STAGE_B;
        const uint32_t sb = sa + TILE_B;

        #pragma unroll
        for (int ks = 0; ks < 4; ks++) {
            uint32_t a[2][4];
            #pragma unroll
            for (int fm = 0; fm < 2; fm++) {
                int row = wm * 32 + fm * 16 + a_row_in;
                int c16 = ks * 2 + a_c16_in;
                LDSM_X4(a[fm][0], a[fm][1], a[fm][2], a[fm][3],
                        sa + SW128((uint32_t)(row * 128 + c16 * 16)));
            }
            uint32_t b[4][4];
            #pragma unroll
            for (int g = 0; g < 4; g++) {
                int row = wn * 64 + g * 16 + b_row_in;
                int c16 = ks * 2 + b_c16_in;
                LDSM_X4(b[g][0], b[g][1], b[g][2], b[g][3],
                        sb + SW128((uint32_t)(row * 128 + c16 * 16)));
            }
            #pragma unroll
            for (int fm = 0; fm < 2; fm++)
                #pragma unroll
                for (int fn = 0; fn < 8; fn++) {
                    const int bg = fn >> 1;
                    if (fn & 1) {
                        MMA_TF32(acc[fm][fn], a[fm][0], a[fm][1], a[fm][2], a[fm][3],
                                 b[bg][2], b[bg][3]);
                    } else {
                        MMA_TF32(acc[fm][fn], a[fm][0], a[fm][1], a[fm][2], a[fm][3],
                                 b[bg][0], b[bg][1]);
                    }
                }
        }
        __syncthreads();
    }

    const int g = lane >> 2;
    const int cpair = (lane & 3) * 2;
    if (round_out) {
        #pragma unroll
        for (int fm = 0; fm < 2; fm++)
            #pragma unroll
            for (int fn = 0; fn < 8; fn++) {
                int r = m0 + wm * 32 + fm * 16 + g;
                int c = n0 + wn * 64 + fn * 8 + cpair;
                *(uint2*)&Cout[(size_t)r * N + c] =
                    make_uint2(f2tf32(acc[fm][fn][0]), f2tf32(acc[fm][fn][1]));
                *(uint2*)&Cout[(size_t)(r + 8) * N + c] =
                    make_uint2(f2tf32(acc[fm][fn][2]), f2tf32(acc[fm][fn][3]));
            }
    } else {
        #pragma unroll
        for (int fm = 0; fm < 2; fm++)
            #pragma unroll
            for (int fn = 0; fn < 8; fn++) {
                int r = m0 + wm * 32 + fm * 16 + g;
                int c = n0 + wn * 64 + fn * 8 + cpair;
                *(float2*)&Cout[(size_t)r * N + c] =
                    make_float2(acc[fm][fn][0], acc[fm][fn][1]);
                *(float2*)&Cout[(size_t)(r + 8) * N + c] =
                    make_float2(acc[fm][fn][2], acc[fm][fn][3]);
            }
    }
}

// ===========================================================================
// Sliding-window attention, tf32 mma.sync, cp.async K pipeline, fused rowmax.
// qkv must hold tf32-rounded values (copied raw).
// ===========================================================================
#define QT 64
#define KT 64
#define NKT 5
#define NK  (NKT*KT)      // 320
#define SPITCH 324
#define PMP 12            // pmax pitch (10 used)

// float offsets in dynamic smem
#define OFF_Q   0                      // 4096 floats (2 subs x 2048)
#define OFF_KV  4096                   // 8192 floats (2 bufs x 4096)
#define OFF_S   12288                  // 20736
#define OFF_PM  33024                  // 64*PMP = 768
#define OFF_RED 33792                  // 256
#define OFF_RS  34048                  // 64
#define ATTN_SMEM_FLOATS 34112

__global__ __launch_bounds__(256) void attn_mma(const float* __restrict__ qkv,
                                                float* __restrict__ y) {
    extern __shared__ float sh[];
    float* S      = sh + OFF_S;
    float* pmax   = sh + OFF_PM;
    float* red    = sh + OFF_RED;
    float* rowsum = sh + OFF_RS;
    uint32_t* Su  = (uint32_t*)S;

    const int tid  = threadIdx.x;
    const int lane = tid & 31;
    const int wid  = tid >> 5;
    const int wm   = wid & 3;
    const int wn   = wid >> 2;
    const int q0 = blockIdx.x * QT;
    const int h  = blockIdx.y;
    const int b  = blockIdx.z;
    const int kstart = q0 - MEMW;

    const float* qbase = qkv + (size_t)b * TT * QKVN + h * DD;
    const float* kbase = qbase + CC;
    const float* vbase = qbase + 2 * CC;

    const uint32_t uQ  = smem_u32(sh) + OFF_Q * 4;
    const uint32_t uKV = smem_u32(sh) + OFF_KV * 4;

    const int a_row_in = (lane & 15);
    const int a_c16_in = (lane >> 4);
    const int b_row_in = (lane & 7) + ((lane >> 4) << 3);
    const int b_c16_in = ((lane >> 3) & 1);
    const int g  = lane >> 2;
    const int c2 = (lane & 3) * 2;

    // ---- async load of Q tile (unpredicated) + K tile 0 -> group 0 ----
    #pragma unroll
    for (int it = 0; it < 4; it++) {
        int idx = it * 256 + tid;
        int row = idx >> 4;
        int c16 = idx & 15;
        uint32_t dst = uQ + (c16 >> 3) * 8192
                     + SW128((uint32_t)(row * 128 + (c16 & 7) * 16));
        cp_async16(dst, &qbase[(size_t)(q0 + row) * QKVN + c16 * 4]);
    }
    auto issue_k = [&](int kt) {
        const uint32_t buf = uKV + (kt & 1) * 16384;
        const int kb = kstart + kt * KT;
        #pragma unroll
        for (int it = 0; it < 4; it++) {
            int idx = it * 256 + tid;
            int row = idx >> 4;
            int c16 = idx & 15;
            int gk  = kb + row;
            uint32_t dst = buf + (c16 >> 3) * 8192
                         + SW128((uint32_t)(row * 128 + (c16 & 7) * 16));
            const float* src = (gk >= 0)
                ? &kbase[(size_t)gk * QKVN + c16 * 4] : kbase;
            cp_async16_z(dst, src, (gk >= 0) ? 16 : 0);
        }
    };
    issue_k(0);
    CP_COMMIT();

    // ---- score phase, double-buffered K ----
    for (int kt = 0; kt < NKT; kt++) {
        __syncthreads();             // all warps done reading buf (kt+1)&1
        if (kt + 1 < NKT) {
            issue_k(kt + 1);
            CP_COMMIT();
            CP_WAIT(1);
        } else {
            CP_WAIT(0);
        }
        __syncthreads();             // K(kt) (and Q on kt=0) visible

        const int kb = kstart + kt * KT;
        const uint32_t ub = uKV + (kt & 1) * 16384;

        float acc[4][4];
        #pragma unroll
        for (int i = 0; i < 4; i++)
            #pragma unroll
            for (int j = 0; j < 4; j++) acc[i][j] = 0.f;

        #pragma unroll
        for (int ks = 0; ks < 8; ks++) {
            const int sub = ks >> 2;
            const int cc  = (ks & 3) * 2;
            uint32_t a[4];
            {
                int row = wm * 16 + a_row_in;
                int c16 = cc + a_c16_in;
                LDSM_X4(a[0], a[1], a[2], a[3],
                        uQ + sub * 8192 + SW128((uint32_t)(row * 128 + c16 * 16)));
            }
            uint32_t bf[2][4];
            #pragma unroll
            for (int g2 = 0; g2 < 2; g2++) {
                int row = wn * 32 + g2 * 16 + b_row_in;
                int c16 = cc + b_c16_in;
                LDSM_X4(bf[g2][0], bf[g2][1], bf[g2][2], bf[g2][3],
                        ub + sub * 8192 + SW128((uint32_t)(row * 128 + c16 * 16)));
            }
            #pragma unroll
            for (int fn = 0; fn < 4; fn++) {
                const int bg = fn >> 1;
                if (fn & 1) {
                    MMA_TF32(acc[fn], a[0], a[1], a[2], a[3], bf[bg][2], bf[bg][3]);
                } else {
                    MMA_TF32(acc[fn], a[0], a[1], a[2], a[3], bf[bg][0], bf[bg][1]);
                }
            }
        }

        // masked store + fused row-max
        const int r0  = wm * 16 + g;
        const int qi0 = q0 + r0;
        const int qi1 = qi0 + 8;
        float mx0 = -1e30f, mx1 = -1e30f;
        #pragma unroll
        for (int fn = 0; fn < 4; fn++) {
            int c  = wn * 32 + fn * 8 + c2;
            int kj = kb + c;
            #pragma unroll
            for (int jj = 0; jj < 2; jj++) {
                int k = kj + jj;
                bool ok0 = (k >= 0) && (k <= qi0) && (qi0 - k <= MEMW);
                bool ok1 = (k >= 0) && (k <= qi1) && (qi1 - k <= MEMW);
                float v0 = ok0 ? acc[fn][jj] * 0.125f : -1e30f;
                float v1 = ok1 ? acc[fn][2 + jj] * 0.125f : -1e30f;
                S[r0 * SPITCH + kt * KT + c + jj] = v0;
                S[(r0 + 8) * SPITCH + kt * KT + c + jj] = v1;
                mx0 = fmaxf(mx0, v0);
                mx1 = fmaxf(mx1, v1);
            }
        }
        mx0 = fmaxf(mx0, __shfl_xor_sync(0xFFFFFFFF, mx0, 1));
        mx0 = fmaxf(mx0, __shfl_xor_sync(0xFFFFFFFF, mx0, 2));
        mx1 = fmaxf(mx1, __shfl_xor_sync(0xFFFFFFFF, mx1, 1));
        mx1 = fmaxf(mx1, __shfl_xor_sync(0xFFFFFFFF, mx1, 2));
        if ((lane & 3) == 0) {
            pmax[r0 * PMP + kt * 2 + wn] = mx0;
            pmax[(r0 + 8) * PMP + kt * 2 + wn] = mx1;
        }
    }
    __syncthreads();

    // ---- softmax: single exp+sum pass, max from pmax ----
    {
        int r = tid >> 2;
        int s = tid & 3;
        float mx = -1e30f;
        #pragma unroll
        for (int i = 0; i < 2 * NKT; i++) mx = fmaxf(mx, pmax[r * PMP + i]);
        float sum = 0.f;
        for (int c = s; c < NK; c += 4) {
            float e = __expf(S[r * SPITCH + c] - mx);
            Su[r * SPITCH + c] = f2tf32(e);
            sum += e;
        }
        red[r * 4 + s] = sum;
        __syncthreads();
        if (s == 0)
            rowsum[r] = red[r * 4 + 0] + red[r * 4 + 1] +
                        red[r * 4 + 2] + red[r * 4 + 3];
    }

    // ---- PV phase: register-pipelined V transpose, single smem buffer ----
    float oacc[4][4];
    #pragma unroll
    for (int i = 0; i < 4; i++)
        #pragma unroll
        for (int j = 0; j < 4; j++) oacc[i][j] = 0.f;

    const int v_kk0 = tid & 15;
    const int v_d4  = tid >> 4;
    float4 vreg[4];

    auto load_v = [&](int kt) {
        #pragma unroll
        for (int it = 0; it < 4; it++) {
            int kk = v_kk0 + 16 * it;
            int gk = kstart + kt * KT + kk;
            float4 v = make_float4(0.f, 0.f, 0.f, 0.f);
            if (gk >= 0) v = *(const float4*)&vbase[(size_t)gk * QKVN + v_d4 * 4];
            vreg[it] = v;
        }
    };
    load_v(0);

    for (int kt = 0; kt < NKT; kt++) {
        __syncthreads();              // everyone done reading V buffer
        #pragma unroll
        for (int it = 0; it < 4; it++) {
            int kk = v_kk0 + 16 * it;
            int sub = kk >> 5;
            int k5  = kk & 31;
            float vv[4] = {vreg[it].x, vreg[it].y, vreg[it].z, vreg[it].w};
            #pragma unroll
            for (int j = 0; j < 4; j++) {
                uint32_t byte = SW128((uint32_t)((v_d4 * 4 + j) * 128 + k5 * 4));
                *(uint32_t*)((char*)sh + OFF_KV * 4 + sub * 8192 + byte) =
                    __float_as_uint(vv[j]);
            }
        }
        if (kt + 1 < NKT) load_v(kt + 1);   // LDG latency overlaps mma below
        __syncthreads();

        #pragma unroll
        for (int ks = 0; ks < 8; ks++) {
            const int key0 = kt * KT + ks * 8;
            const int sub  = ks >> 2;
            const int cc   = (ks & 3) * 2;
            uint32_t a[4];
            {
                int r0 = wm * 16 + g;
                int kx = key0 + (lane & 3);
                a[0] = Su[r0 * SPITCH + kx];
                a[1] = Su[(r0 + 8) * SPITCH + kx];
                a[2] = Su[r0 * SPITCH + kx + 4];
                a[3] = Su[(r0 + 8) * SPITCH + kx + 4];
            }
            uint32_t bf[2][4];
            #pragma unroll
            for (int g2 = 0; g2 < 2; g2++) {
                int row = wn * 32 + g2 * 16 + b_row_in;
                int c16 = cc + b_c16_in;
                LDSM_X4(bf[g2][0], bf[g2][1], bf[g2][2], bf[g2][3],
                        uKV + sub * 8192 + SW128((uint32_t)(row * 128 + c16 * 16)));
            }
            #pragma unroll
            for (int fn = 0; fn < 4; fn++) {
                const int bg = fn >> 1;
                if (fn & 1) {
                    MMA_TF32(oacc[fn], a[0], a[1], a[2], a[3], bf[bg][2], bf[bg][3]);
                } else {
                    MMA_TF32(oacc[fn], a[0], a[1], a[2], a[3], bf[bg][0], bf[bg][1]);
                }
            }
        }
    }
    __syncthreads();

    // ---- epilogue: normalize, tf32-round, store ----
    {
        int r0 = wm * 16 + g;
        float inv0 = 1.0f / rowsum[r0];
        float inv1 = 1.0f / rowsum[r0 + 8];
        #pragma unroll
        for (int fn = 0; fn < 4; fn++) {
            int col = wn * 32 + fn * 8 + c2;
            float* p0 = &y[(size_t)(b * TT + q0 + r0) * CC + h * DD + col];
            float* p1 = &y[(size_t)(b * TT + q0 + r0 + 8) * CC + h * DD + col];
            *(uint2*)p0 = make_uint2(f2tf32(oacc[fn][0] * inv0),
                                     f2tf32(oacc[fn][1] * inv0));
            *(uint2*)p1 = make_uint2(f2tf32(oacc[fn][2] * inv1),
                                     f2tf32(oacc[fn][3] * inv1));
        }
    }
}

// ===========================================================================
extern "C" void kernel_launch(void* const* d_in, const int* in_sizes, int n_in,
                              void* d_out, int out_size) {
    const float* x      = (const float*)d_in[0];
    const float* w_attn = (const float*)d_in[1];
    const float* w_proj = (const float*)d_in[2];
    float* out = (float*)d_out;

    float *qkv = nullptr, *yb = nullptr, *xc = nullptr, *wac = nullptr, *wpc = nullptr;
    cudaGetSymbolAddress((void**)&qkv, g_qkv);
    cudaGetSymbolAddress((void**)&yb,  g_y);
    cudaGetSymbolAddress((void**)&xc,  g_xc);
    cudaGetSymbolAddress((void**)&wac, g_wac);
    cudaGetSymbolAddress((void**)&wpc, g_wpc);

    const int attn_smem = ATTN_SMEM_FLOATS * (int)sizeof(float);
    cudaFuncSetAttribute(attn_mma,
                         cudaFuncAttributeMaxDynamicSharedMemorySize, attn_smem);
    cudaFuncSetAttribute(gemm_ca,
                         cudaFuncAttributeMaxDynamicSharedMemorySize, GEMM_SMEM);

    // 0) tf32 pre-convert of x, w_attn, w_proj
    {
        int total4 = (XN + WAN + WPN) / 4;
        convert_kernel<<<(total4 + 255) / 256, 256>>>(x, w_attn, w_proj);
    }
    // 1) QKV projection (tf32-rounded output)
    {
        dim3 grid(QKVN / GBN, M_TOT / GBM);
        gemm_ca<<<grid, 256, GEMM_SMEM>>>(xc, wac, qkv, M_TOT, QKVN, CC, 1);
    }
    // 2) windowed attention -> y (tf32-rounded)
    {
        dim3 grid(TT / QT, HH, BB);
        attn_mma<<<grid, 256, attn_smem>>>(qkv, yb);
    }
    // 3) output projection (fp32 output)
    {
        dim3 grid(CC / GBN, M_TOT / GBM);
        gemm_ca<<<grid, 256, GEMM_SMEM>>>(yb, wpc, out, M_TOT, CC, CC, 0);
    }
}

// round 7
// speedup vs baseline: 3.9699x; 1.1306x over previous
#include <cuda_runtime.h>
#include <math.h>
#include <stdint.h>

#define BB   2
#define TT   4096
#define CC   512
#define HH   8
#define DD   64
#define MEMW 256

#define M_TOT (BB*TT)     // 8192
#define QKVN  (3*CC)      // 1536

#define XN  (M_TOT*CC)
#define WAN (QKVN*CC)
#define WPN (CC*CC)

// scratch (allocation-free contract: device globals)
__device__ float g_qkv[BB*TT*3*CC];   // [B*T, 3C] tf32-rounded values
__device__ float g_y[BB*TT*CC];       // [B*T, C]  tf32-rounded values
__device__ float g_xc[XN];
__device__ float g_wac[WAN];
__device__ float g_wpc[WPN];

// ===========================================================================
// helpers
// ===========================================================================
__device__ __forceinline__ uint32_t smem_u32(const void* p) {
    uint32_t a;
    asm("{ .reg .u64 t; cvta.to.shared.u64 t, %1; cvt.u32.u64 %0, t; }"
        : "=r"(a) : "l"(p));
    return a;
}
__device__ __forceinline__ uint32_t f2tf32(float f) {
    uint32_t r;
    asm("cvt.rna.tf32.f32 %0, %1;" : "=r"(r) : "f"(f));
    return r;
}
#define SW128(off) ((off) ^ (((off) >> 3) & 0x70))

#define LDSM_X4(r0, r1, r2, r3, addr) \
    asm volatile("ldmatrix.sync.aligned.m8n8.x4.shared.b16 {%0,%1,%2,%3}, [%4];" \
                 : "=r"(r0), "=r"(r1), "=r"(r2), "=r"(r3) : "r"(addr))

#define MMA_TF32(c, a0, a1, a2, a3, b0, b1) \
    asm volatile("mma.sync.aligned.m16n8k8.row.col.f32.tf32.tf32.f32 " \
                 "{%0,%1,%2,%3}, {%4,%5,%6,%7}, {%8,%9}, {%0,%1,%2,%3};" \
                 : "+f"((c)[0]), "+f"((c)[1]), "+f"((c)[2]), "+f"((c)[3]) \
                 : "r"(a0), "r"(a1), "r"(a2), "r"(a3), "r"(b0), "r"(b1))

__device__ __forceinline__ void cp_async16(uint32_t s, const void* g) {
    asm volatile("cp.async.cg.shared.global [%0], [%1], 16;"
                 :: "r"(s), "l"(__cvta_generic_to_global(g)));
}
__device__ __forceinline__ void cp_async16_z(uint32_t s, const void* g, int sz) {
    asm volatile("cp.async.cg.shared.global [%0], [%1], 16, %2;"
                 :: "r"(s), "l"(__cvta_generic_to_global(g)), "r"(sz));
}
#define CP_COMMIT() asm volatile("cp.async.commit_group;" ::: "memory")
#define CP_WAIT(n)  asm volatile("cp.async.wait_group %0;" :: "n"(n) : "memory")

// ===========================================================================
// pre-convert: tf32-round x, w_attn, w_proj
// ===========================================================================
__global__ __launch_bounds__(256) void convert_kernel(const float* __restrict__ x,
                                                      const float* __restrict__ wa,
                                                      const float* __restrict__ wp) {
    const int i4 = blockIdx.x * 256 + threadIdx.x;
    const int total4 = (XN + WAN + WPN) / 4;
    if (i4 >= total4) return;
    const float* src;
    float* dst;
    int j4 = i4;
    if (j4 < XN / 4)                  { src = x;  dst = g_xc; }
    else if ((j4 -= XN / 4) < WAN / 4){ src = wa; dst = g_wac; }
    else                              { j4 -= WAN / 4; src = wp; dst = g_wpc; }
    float4 v = *(const float4*)&src[j4 * 4];
    uint4 o = make_uint4(f2tf32(v.x), f2tf32(v.y), f2tf32(v.z), f2tf32(v.w));
    *(uint4*)&dst[j4 * 4] = o;
}

// ===========================================================================
// tf32 mma.sync GEMM (NT), cp.async 3-stage pipeline (unchanged from R6)
// ===========================================================================
#define GBM 128
#define GBN 128
#define GBK 32
#define STAGES 3
#define TILE_B (GBM * GBK * 4)
#define STAGE_B (2 * TILE_B)
#define GEMM_SMEM (STAGES * STAGE_B)

__global__ __launch_bounds__(256) void gemm_ca(const float* __restrict__ A,
                                               const float* __restrict__ W,
                                               float* __restrict__ Cout,
                                               int M, int N, int K, int round_out) {
    extern __shared__ char dynsm[];
    const uint32_t smb = smem_u32(dynsm);

    const int tid  = threadIdx.x;
    const int lane = tid & 31;
    const int wid  = tid >> 5;
    const int wm   = wid & 3;
    const int wn   = wid >> 2;
    const int m0 = blockIdx.y * GBM;
    const int n0 = blockIdx.x * GBN;

    const int crow = tid >> 3;
    const int cc16 = tid & 7;
    const uint32_t cbyte = SW128((uint32_t)(crow * 128 + cc16 * 16));

    const int nk = K / GBK;

    auto issue_copy = [&](int kt) {
        const int s = kt % STAGES;
        const int k0 = kt * GBK;
        const uint32_t sa = smb + s * STAGE_B;
        const uint32_t sb = sa + TILE_B;
        #pragma unroll
        for (int it = 0; it < 4; it++) {
            const int row = crow + it * 32;
            cp_async16(sa + cbyte + it * 32 * 128,
                       &A[(size_t)(m0 + row) * K + k0 + cc16 * 4]);
        }
        #pragma unroll
        for (int it = 0; it < 4; it++) {
            const int row = crow + it * 32;
            cp_async16(sb + cbyte + it * 32 * 128,
                       &W[(size_t)(n0 + row) * K + k0 + cc16 * 4]);
        }
    };

    float acc[2][8][4];
    #pragma unroll
    for (int i = 0; i < 2; i++)
        #pragma unroll
        for (int j = 0; j < 8; j++)
            #pragma unroll
            for (int k = 0; k < 4; k++) acc[i][j][k] = 0.f;

    const int a_row_in = (lane & 15);
    const int a_c16_in = (lane >> 4);
    const int b_row_in = (lane & 7) + ((lane >> 4) << 3);
    const int b_c16_in = ((lane >> 3) & 1);

    #pragma unroll
    for (int s = 0; s < STAGES - 1; s++) {
        issue_copy(s);
        CP_COMMIT();
    }

    for (int kt = 0; kt < nk; kt++) {
        CP_WAIT(STAGES - 2);
        __syncthreads();

        if (kt + STAGES - 1 < nk) issue_copy(kt + STAGES - 1);
        CP_COMMIT();

        const uint32_t sa = smb + (kt % STAGES) * STAGE_B;
        const uint32_t sb = sa + TILE_B;

        #pragma unroll
        for (int ks = 0; ks < 4; ks++) {
            uint32_t a[2][4];
            #pragma unroll
            for (int fm = 0; fm < 2; fm++) {
                int row = wm * 32 + fm * 16 + a_row_in;
                int c16 = ks * 2 + a_c16_in;
                LDSM_X4(a[fm][0], a[fm][1], a[fm][2], a[fm][3],
                        sa + SW128((uint32_t)(row * 128 + c16 * 16)));
            }
            uint32_t b[4][4];
            #pragma unroll
            for (int g = 0; g < 4; g++) {
                int row = wn * 64 + g * 16 + b_row_in;
                int c16 = ks * 2 + b_c16_in;
                LDSM_X4(b[g][0], b[g][1], b[g][2], b[g][3],
                        sb + SW128((uint32_t)(row * 128 + c16 * 16)));
            }
            #pragma unroll
            for (int fm = 0; fm < 2; fm++)
                #pragma unroll
                for (int fn = 0; fn < 8; fn++) {
                    const int bg = fn >> 1;
                    if (fn & 1) {
                        MMA_TF32(acc[fm][fn], a[fm][0], a[fm][1], a[fm][2], a[fm][3],
                                 b[bg][2], b[bg][3]);
                    } else {
                        MMA_TF32(acc[fm][fn], a[fm][0], a[fm][1], a[fm][2], a[fm][3],
                                 b[bg][0], b[bg][1]);
                    }
                }
        }
        __syncthreads();
    }

    const int g = lane >> 2;
    const int cpair = (lane & 3) * 2;
    if (round_out) {
        #pragma unroll
        for (int fm = 0; fm < 2; fm++)
            #pragma unroll
            for (int fn = 0; fn < 8; fn++) {
                int r = m0 + wm * 32 + fm * 16 + g;
                int c = n0 + wn * 64 + fn * 8 + cpair;
                *(uint2*)&Cout[(size_t)r * N + c] =
                    make_uint2(f2tf32(acc[fm][fn][0]), f2tf32(acc[fm][fn][1]));
                *(uint2*)&Cout[(size_t)(r + 8) * N + c] =
                    make_uint2(f2tf32(acc[fm][fn][2]), f2tf32(acc[fm][fn][3]));
            }
    } else {
        #pragma unroll
        for (int fm = 0; fm < 2; fm++)
            #pragma unroll
            for (int fn = 0; fn < 8; fn++) {
                int r = m0 + wm * 32 + fm * 16 + g;
                int c = n0 + wn * 64 + fn * 8 + cpair;
                *(float2*)&Cout[(size_t)r * N + c] =
                    make_float2(acc[fm][fn][0], acc[fm][fn][1]);
                *(float2*)&Cout[(size_t)(r + 8) * N + c] =
                    make_float2(acc[fm][fn][2], acc[fm][fn][3]);
            }
    }
}

// ===========================================================================
// Flash-style sliding-window attention, tf32 mma.sync, online softmax.
// One CTA = 64 queries of one (b,h); 5 key tiles; smem ~84KB -> 2 CTA/SM.
// ===========================================================================
#define QT 64
#define KT 64
#define NKT 5
#define PPITCH 68

// float offsets
#define AOFF_Q   0            // 4096 (2 subs x [64][32] SW128)
#define AOFF_K   4096         // 2 bufs x 4096
#define AOFF_V   12288        // 4096 (V^T, 2 subs)
#define AOFF_P   16384        // 64*68 = 4352 (tf32 bits)
#define AOFF_PM  20736        // 64*2
#define AOFF_SM  20864        // 64*2
#define ATTN_SMEM_FLOATS 20992

__global__ __launch_bounds__(256, 2) void attn_flash(const float* __restrict__ qkv,
                                                     float* __restrict__ y) {
    extern __shared__ float sh[];
    float* pmax = sh + AOFF_PM;
    float* psum = sh + AOFF_SM;
    uint32_t* Pu = (uint32_t*)(sh + AOFF_P);

    const int tid  = threadIdx.x;
    const int lane = tid & 31;
    const int wid  = tid >> 5;
    const int wm   = wid & 3;
    const int wn   = wid >> 2;
    const int q0 = blockIdx.x * QT;
    const int h  = blockIdx.y;
    const int b  = blockIdx.z;
    const int kstart = q0 - MEMW;

    const float* qbase = qkv + (size_t)b * TT * QKVN + h * DD;
    const float* kbase = qbase + CC;
    const float* vbase = qbase + 2 * CC;

    const uint32_t uQ = smem_u32(sh) + AOFF_Q * 4;
    const uint32_t uK = smem_u32(sh) + AOFF_K * 4;
    const uint32_t uV = smem_u32(sh) + AOFF_V * 4;

    const int a_row_in = (lane & 15);
    const int a_c16_in = (lane >> 4);
    const int b_row_in = (lane & 7) + ((lane >> 4) << 3);
    const int b_c16_in = ((lane >> 3) & 1);
    const int g  = lane >> 2;
    const int c2 = (lane & 3) * 2;
    const int r0 = wm * 16 + g;

    // ---- prologue: async Q + K0 ----
    #pragma unroll
    for (int it = 0; it < 4; it++) {
        int idx = it * 256 + tid;
        int row = idx >> 4;
        int c16 = idx & 15;
        uint32_t dst = uQ + (c16 >> 3) * 8192
                     + SW128((uint32_t)(row * 128 + (c16 & 7) * 16));
        cp_async16(dst, &qbase[(size_t)(q0 + row) * QKVN + c16 * 4]);
    }
    auto issue_k = [&](int kt) {
        const uint32_t buf = uK + (kt & 1) * 16384;
        const int kb = kstart + kt * KT;
        #pragma unroll
        for (int it = 0; it < 4; it++) {
            int idx = it * 256 + tid;
            int row = idx >> 4;
            int c16 = idx & 15;
            int gk  = kb + row;
            uint32_t dst = buf + (c16 >> 3) * 8192
                         + SW128((uint32_t)(row * 128 + (c16 & 7) * 16));
            const float* src = (gk >= 0)
                ? &kbase[(size_t)gk * QKVN + c16 * 4] : kbase;
            cp_async16_z(dst, src, (gk >= 0) ? 16 : 0);
        }
    };
    issue_k(0);
    CP_COMMIT();

    // V register prefetch
    const int v_kk0 = tid & 15;
    const int v_d4  = tid >> 4;
    float4 vreg[4];
    auto load_v = [&](int kt) {
        #pragma unroll
        for (int it = 0; it < 4; it++) {
            int kk = v_kk0 + 16 * it;
            int gk = kstart + kt * KT + kk;
            float4 v = make_float4(0.f, 0.f, 0.f, 0.f);
            if (gk >= 0) v = *(const float4*)&vbase[(size_t)gk * QKVN + v_d4 * 4];
            vreg[it] = v;
        }
    };
    load_v(0);

    float m_old0 = -1e30f, m_old1 = -1e30f;
    float srun0 = 0.f, srun1 = 0.f;
    float oacc[4][4];
    #pragma unroll
    for (int i = 0; i < 4; i++)
        #pragma unroll
        for (int j = 0; j < 4; j++) oacc[i][j] = 0.f;

    for (int kt = 0; kt < NKT; kt++) {
        CP_WAIT(0);
        __syncthreads();               // K(kt)+Q visible; prev PV/P/V reads done
        if (kt + 1 < NKT) { issue_k(kt + 1); CP_COMMIT(); }

        const int kb = kstart + kt * KT;
        const uint32_t ub = uK + (kt & 1) * 16384;

        // ---- score mma ----
        float acc[4][4];
        #pragma unroll
        for (int i = 0; i < 4; i++)
            #pragma unroll
            for (int j = 0; j < 4; j++) acc[i][j] = 0.f;

        #pragma unroll
        for (int ks = 0; ks < 8; ks++) {
            const int sub = ks >> 2;
            const int cc  = (ks & 3) * 2;
            uint32_t a[4];
            {
                int row = wm * 16 + a_row_in;
                int c16 = cc + a_c16_in;
                LDSM_X4(a[0], a[1], a[2], a[3],
                        uQ + sub * 8192 + SW128((uint32_t)(row * 128 + c16 * 16)));
            }
            uint32_t bf[2][4];
            #pragma unroll
            for (int g2 = 0; g2 < 2; g2++) {
                int row = wn * 32 + g2 * 16 + b_row_in;
                int c16 = cc + b_c16_in;
                LDSM_X4(bf[g2][0], bf[g2][1], bf[g2][2], bf[g2][3],
                        ub + sub * 8192 + SW128((uint32_t)(row * 128 + c16 * 16)));
            }
            #pragma unroll
            for (int fn = 0; fn < 4; fn++) {
                const int bg = fn >> 1;
                if (fn & 1) {
                    MMA_TF32(acc[fn], a[0], a[1], a[2], a[3], bf[bg][2], bf[bg][3]);
                } else {
                    MMA_TF32(acc[fn], a[0], a[1], a[2], a[3], bf[bg][0], bf[bg][1]);
                }
            }
        }

        // ---- V^T store for this tile (prev tile's PV done at sync above) ----
        #pragma unroll
        for (int it = 0; it < 4; it++) {
            int kk = v_kk0 + 16 * it;
            int sub = kk >> 5;
            int k5  = kk & 31;
            float vv[4] = {vreg[it].x, vreg[it].y, vreg[it].z, vreg[it].w};
            #pragma unroll
            for (int j = 0; j < 4; j++) {
                uint32_t byte = SW128((uint32_t)((v_d4 * 4 + j) * 128 + k5 * 4));
                *(uint32_t*)((char*)sh + AOFF_V * 4 + sub * 8192 + byte) =
                    __float_as_uint(vv[j]);
            }
        }
        if (kt + 1 < NKT) load_v(kt + 1);

        // ---- mask + scale + per-warp row max ----
        const int qi0 = q0 + r0;
        const int qi1 = qi0 + 8;
        float mx0 = -1e30f, mx1 = -1e30f;
        #pragma unroll
        for (int fn = 0; fn < 4; fn++) {
            int c  = wn * 32 + fn * 8 + c2;
            int kj = kb + c;
            #pragma unroll
            for (int jj = 0; jj < 2; jj++) {
                int k = kj + jj;
                bool ok0 = (k >= 0) && (k <= qi0) && (qi0 - k <= MEMW);
                bool ok1 = (k >= 0) && (k <= qi1) && (qi1 - k <= MEMW);
                acc[fn][jj]     = ok0 ? acc[fn][jj]     * 0.125f : -1e30f;
                acc[fn][2 + jj] = ok1 ? acc[fn][2 + jj] * 0.125f : -1e30f;
                mx0 = fmaxf(mx0, acc[fn][jj]);
                mx1 = fmaxf(mx1, acc[fn][2 + jj]);
            }
        }
        mx0 = fmaxf(mx0, __shfl_xor_sync(0xFFFFFFFF, mx0, 1));
        mx0 = fmaxf(mx0, __shfl_xor_sync(0xFFFFFFFF, mx0, 2));
        mx1 = fmaxf(mx1, __shfl_xor_sync(0xFFFFFFFF, mx1, 1));
        mx1 = fmaxf(mx1, __shfl_xor_sync(0xFFFFFFFF, mx1, 2));
        if ((lane & 3) == 0) {
            pmax[r0 * 2 + wn] = mx0;
            pmax[(r0 + 8) * 2 + wn] = mx1;
        }
        __syncthreads();               // pmax + V^T visible

        // ---- online max update, exp, P store, partial sums ----
        float m0 = fmaxf(m_old0, fmaxf(pmax[r0 * 2], pmax[r0 * 2 + 1]));
        float m1 = fmaxf(m_old1, fmaxf(pmax[(r0 + 8) * 2], pmax[(r0 + 8) * 2 + 1]));
        float f0 = __expf(m_old0 - m0);
        float f1 = __expf(m_old1 - m1);
        m_old0 = m0;
        m_old1 = m1;

        float s0 = 0.f, s1 = 0.f;
        #pragma unroll
        for (int fn = 0; fn < 4; fn++) {
            int c = wn * 32 + fn * 8 + c2;
            #pragma unroll
            for (int jj = 0; jj < 2; jj++) {
                float p0 = __expf(acc[fn][jj] - m0);
                float p1 = __expf(acc[fn][2 + jj] - m1);
                Pu[r0 * PPITCH + c + jj] = f2tf32(p0);
                Pu[(r0 + 8) * PPITCH + c + jj] = f2tf32(p1);
                s0 += p0;
                s1 += p1;
            }
        }
        s0 += __shfl_xor_sync(0xFFFFFFFF, s0, 1);
        s0 += __shfl_xor_sync(0xFFFFFFFF, s0, 2);
        s1 += __shfl_xor_sync(0xFFFFFFFF, s1, 1);
        s1 += __shfl_xor_sync(0xFFFFFFFF, s1, 2);
        if ((lane & 3) == 0) {
            psum[r0 * 2 + wn] = s0;
            psum[(r0 + 8) * 2 + wn] = s1;
        }
        // rescale O accumulators
        #pragma unroll
        for (int fn = 0; fn < 4; fn++) {
            oacc[fn][0] *= f0;
            oacc[fn][1] *= f0;
            oacc[fn][2] *= f1;
            oacc[fn][3] *= f1;
        }
        __syncthreads();               // P + psum visible

        srun0 = srun0 * f0 + psum[r0 * 2] + psum[r0 * 2 + 1];
        srun1 = srun1 * f1 + psum[(r0 + 8) * 2] + psum[(r0 + 8) * 2 + 1];

        // ---- PV mma ----
        #pragma unroll
        for (int ks = 0; ks < 8; ks++) {
            const int sub = ks >> 2;
            const int cc  = (ks & 3) * 2;
            uint32_t a[4];
            {
                int kx = ks * 8 + (lane & 3);
                a[0] = Pu[r0 * PPITCH + kx];
                a[1] = Pu[(r0 + 8) * PPITCH + kx];
                a[2] = Pu[r0 * PPITCH + kx + 4];
                a[3] = Pu[(r0 + 8) * PPITCH + kx + 4];
            }
            uint32_t bf[2][4];
            #pragma unroll
            for (int g2 = 0; g2 < 2; g2++) {
                int row = wn * 32 + g2 * 16 + b_row_in;
                int c16 = cc + b_c16_in;
                LDSM_X4(bf[g2][0], bf[g2][1], bf[g2][2], bf[g2][3],
                        uV + sub * 8192 + SW128((uint32_t)(row * 128 + c16 * 16)));
            }
            #pragma unroll
            for (int fn = 0; fn < 4; fn++) {
                const int bg = fn >> 1;
                if (fn & 1) {
                    MMA_TF32(oacc[fn], a[0], a[1], a[2], a[3], bf[bg][2], bf[bg][3]);
                } else {
                    MMA_TF32(oacc[fn], a[0], a[1], a[2], a[3], bf[bg][0], bf[bg][1]);
                }
            }
        }
    }

    // ---- epilogue: normalize, tf32-round, store ----
    {
        float inv0 = 1.0f / srun0;
        float inv1 = 1.0f / srun1;
        #pragma unroll
        for (int fn = 0; fn < 4; fn++) {
            int col = wn * 32 + fn * 8 + c2;
            float* p0 = &y[(size_t)(b * TT + q0 + r0) * CC + h * DD + col];
            float* p1 = &y[(size_t)(b * TT + q0 + r0 + 8) * CC + h * DD + col];
            *(uint2*)p0 = make_uint2(f2tf32(oacc[fn][0] * inv0),
                                     f2tf32(oacc[fn][1] * inv0));
            *(uint2*)p1 = make_uint2(f2tf32(oacc[fn][2] * inv1),
                                     f2tf32(oacc[fn][3] * inv1));
        }
    }
}

// ===========================================================================
extern "C" void kernel_launch(void* const* d_in, const int* in_sizes, int n_in,
                              void* d_out, int out_size) {
    const float* x      = (const float*)d_in[0];
    const float* w_attn = (const float*)d_in[1];
    const float* w_proj = (const float*)d_in[2];
    float* out = (float*)d_out;

    float *qkv = nullptr, *yb = nullptr, *xc = nullptr, *wac = nullptr, *wpc = nullptr;
    cudaGetSymbolAddress((void**)&qkv, g_qkv);
    cudaGetSymbolAddress((void**)&yb,  g_y);
    cudaGetSymbolAddress((void**)&xc,  g_xc);
    cudaGetSymbolAddress((void**)&wac, g_wac);
    cudaGetSymbolAddress((void**)&wpc, g_wpc);

    const int attn_smem = ATTN_SMEM_FLOATS * (int)sizeof(float);
    cudaFuncSetAttribute(attn_flash,
                         cudaFuncAttributeMaxDynamicSharedMemorySize, attn_smem);
    cudaFuncSetAttribute(gemm_ca,
                         cudaFuncAttributeMaxDynamicSharedMemorySize, GEMM_SMEM);

    // 0) tf32 pre-convert
    {
        int total4 = (XN + WAN + WPN) / 4;
        convert_kernel<<<(total4 + 255) / 256, 256>>>(x, w_attn, w_proj);
    }
    // 1) QKV projection (tf32-rounded output)
    {
        dim3 grid(QKVN / GBN, M_TOT / GBM);
        gemm_ca<<<grid, 256, GEMM_SMEM>>>(xc, wac, qkv, M_TOT, QKVN, CC, 1);
    }
    // 2) windowed attention -> y (tf32-rounded)
    {
        dim3 grid(TT / QT, HH, BB);
        attn_flash<<<grid, 256, attn_smem>>>(qkv, yb);
    }
    // 3) output projection (fp32 output)
    {
        dim3 grid(CC / GBN, M_TOT / GBM);
        gemm_ca<<<grid, 256, GEMM_SMEM>>>(yb, wpc, out, M_TOT, CC, CC, 0);
    }
}

// round 8
// speedup vs baseline: 7.5003x; 1.8893x over previous
#include <cuda_runtime.h>
#include <cuda_fp16.h>
#include <math.h>
#include <stdint.h>

#define BB   2
#define TT   4096
#define CC   512
#define HH   8
#define DD   64
#define MEMW 256

#define M_TOT (BB*TT)     // 8192
#define QKVN  (3*CC)      // 1536

#define XN  (M_TOT*CC)
#define WAN (QKVN*CC)
#define WPN (CC*CC)

// scratch (allocation-free contract: device globals) — all fp16 now
__device__ __half g_qkv[BB*TT*3*CC];
__device__ __half g_y[BB*TT*CC];
__device__ __half g_xc[XN];
__device__ __half g_wac[WAN];
__device__ __half g_wpc[WPN];

// ===========================================================================
// helpers
// ===========================================================================
__device__ __forceinline__ uint32_t smem_u32(const void* p) {
    uint32_t a;
    asm("{ .reg .u64 t; cvta.to.shared.u64 t, %1; cvt.u32.u64 %0, t; }"
        : "=r"(a) : "l"(p));
    return a;
}
#define SW128(off) ((off) ^ (((off) >> 3) & 0x70))

#define LDSM_X4(r0, r1, r2, r3, addr) \
    asm volatile("ldmatrix.sync.aligned.m8n8.x4.shared.b16 {%0,%1,%2,%3}, [%4];" \
                 : "=r"(r0), "=r"(r1), "=r"(r2), "=r"(r3) : "r"(addr))

#define LDSM_X4T(r0, r1, r2, r3, addr) \
    asm volatile("ldmatrix.sync.aligned.m8n8.x4.trans.shared.b16 {%0,%1,%2,%3}, [%4];" \
                 : "=r"(r0), "=r"(r1), "=r"(r2), "=r"(r3) : "r"(addr))

#define MMA_F16(c, a0, a1, a2, a3, b0, b1) \
    asm volatile("mma.sync.aligned.m16n8k16.row.col.f32.f16.f16.f32 " \
                 "{%0,%1,%2,%3}, {%4,%5,%6,%7}, {%8,%9}, {%0,%1,%2,%3};" \
                 : "+f"((c)[0]), "+f"((c)[1]), "+f"((c)[2]), "+f"((c)[3]) \
                 : "r"(a0), "r"(a1), "r"(a2), "r"(a3), "r"(b0), "r"(b1))

__device__ __forceinline__ void cp_async16(uint32_t s, const void* g) {
    asm volatile("cp.async.cg.shared.global [%0], [%1], 16;"
                 :: "r"(s), "l"(__cvta_generic_to_global(g)));
}
__device__ __forceinline__ void cp_async16_z(uint32_t s, const void* g, int sz) {
    asm volatile("cp.async.cg.shared.global [%0], [%1], 16, %2;"
                 :: "r"(s), "l"(__cvta_generic_to_global(g)), "r"(sz));
}
#define CP_COMMIT() asm volatile("cp.async.commit_group;" ::: "memory")
#define CP_WAIT(n)  asm volatile("cp.async.wait_group %0;" :: "n"(n) : "memory")

__device__ __forceinline__ uint32_t packh2(float a, float b) {
    __half2 h = __floats2half2_rn(a, b);
    return *(uint32_t*)&h;
}

// ===========================================================================
// pre-convert: fp32 -> fp16 for x, w_attn, w_proj (8 floats / thread)
// ===========================================================================
__global__ __launch_bounds__(256) void convert_kernel(const float* __restrict__ x,
                                                      const float* __restrict__ wa,
                                                      const float* __restrict__ wp) {
    const int i8 = blockIdx.x * 256 + threadIdx.x;
    const int total8 = (XN + WAN + WPN) / 8;
    if (i8 >= total8) return;
    const float* src;
    __half* dst;
    int j = i8;
    if (j < XN / 8)                   { src = x;  dst = g_xc; }
    else if ((j -= XN / 8) < WAN / 8) { src = wa; dst = g_wac; }
    else                              { j -= WAN / 8; src = wp; dst = g_wpc; }
    float4 v0 = ((const float4*)src)[j * 2];
    float4 v1 = ((const float4*)src)[j * 2 + 1];
    uint4 o = make_uint4(packh2(v0.x, v0.y), packh2(v0.z, v0.w),
                         packh2(v1.x, v1.y), packh2(v1.z, v1.w));
    ((uint4*)dst)[j] = o;
}

// ===========================================================================
// fp16 mma.sync GEMM (NT): C[m,n] = sum_k A[m,k] * W[n,k]
// CTA 128x128, BK=64 (one 128B smem row), 3-stage cp.async, 8 warps (4m x 2n).
// round_out!=0 -> fp16 output, else fp32.
// ===========================================================================
#define GBM 128
#define GBN 128
#define GBK 64
#define STAGES 3
#define TILE_B (GBM * 128)              // 16384 bytes
#define STAGE_B (2 * TILE_B)            // 32768
#define GEMM_SMEM (STAGES * STAGE_B)    // 98304

__global__ __launch_bounds__(256) void gemm_fp16(const __half* __restrict__ A,
                                                 const __half* __restrict__ W,
                                                 void* __restrict__ CoutV,
                                                 int M, int N, int K, int round_out) {
    extern __shared__ char dynsm[];
    const uint32_t smb = smem_u32(dynsm);

    const int tid  = threadIdx.x;
    const int lane = tid & 31;
    const int wid  = tid >> 5;
    const int wm   = wid & 3;
    const int wn   = wid >> 2;
    const int m0 = blockIdx.y * GBM;
    const int n0 = blockIdx.x * GBN;

    const int crow = tid >> 3;          // 0..31
    const int cc   = tid & 7;
    const uint32_t cbyte = SW128((uint32_t)(crow * 128 + cc * 16));

    const int nk = K / GBK;             // 8

    auto issue_copy = [&](int kt) {
        const int s = kt % STAGES;
        const int k0 = kt * GBK;
        const uint32_t sa = smb + s * STAGE_B;
        const uint32_t sb = sa + TILE_B;
        #pragma unroll
        for (int it = 0; it < 4; it++) {
            const int row = crow + it * 32;
            cp_async16(sa + cbyte + it * 32 * 128,
                       &A[(size_t)(m0 + row) * K + k0 + cc * 8]);
        }
        #pragma unroll
        for (int it = 0; it < 4; it++) {
            const int row = crow + it * 32;
            cp_async16(sb + cbyte + it * 32 * 128,
                       &W[(size_t)(n0 + row) * K + k0 + cc * 8]);
        }
    };

    float acc[2][8][4];
    #pragma unroll
    for (int i = 0; i < 2; i++)
        #pragma unroll
        for (int j = 0; j < 8; j++)
            #pragma unroll
            for (int k = 0; k < 4; k++) acc[i][j][k] = 0.f;

    // fragment lane geometry (fp16 m16n8k16)
    const int a_row = (lane & 7) + ((lane >> 3) & 1) * 8;   // + m base
    const int a_col = (lane >> 4) * 16;                     // + ks*32 bytes
    const int b_row = (lane & 7) + (lane >> 4) * 8;         // + n base
    const int b_col = ((lane >> 3) & 1) * 16;               // + ks*32 bytes

    #pragma unroll
    for (int s = 0; s < STAGES - 1; s++) {
        issue_copy(s);
        CP_COMMIT();
    }

    for (int kt = 0; kt < nk; kt++) {
        CP_WAIT(STAGES - 2);
        __syncthreads();
        if (kt + STAGES - 1 < nk) issue_copy(kt + STAGES - 1);
        CP_COMMIT();

        const uint32_t sa = smb + (kt % STAGES) * STAGE_B;
        const uint32_t sb = sa + TILE_B;

        #pragma unroll
        for (int ks = 0; ks < 4; ks++) {      // 4 x k16
            uint32_t a[2][4];
            #pragma unroll
            for (int fm = 0; fm < 2; fm++) {
                int row = wm * 32 + fm * 16 + a_row;
                LDSM_X4(a[fm][0], a[fm][1], a[fm][2], a[fm][3],
                        sa + SW128((uint32_t)(row * 128 + ks * 32 + a_col)));
            }
            uint32_t b[4][4];
            #pragma unroll
            for (int bg = 0; bg < 4; bg++) {
                int row = wn * 64 + bg * 16 + b_row;
                LDSM_X4(b[bg][0], b[bg][1], b[bg][2], b[bg][3],
                        sb + SW128((uint32_t)(row * 128 + ks * 32 + b_col)));
            }
            #pragma unroll
            for (int fm = 0; fm < 2; fm++)
                #pragma unroll
                for (int fn = 0; fn < 8; fn++) {
                    const int bg = fn >> 1;
                    if (fn & 1) {
                        MMA_F16(acc[fm][fn], a[fm][0], a[fm][1], a[fm][2], a[fm][3],
                                b[bg][2], b[bg][3]);
                    } else {
                        MMA_F16(acc[fm][fn], a[fm][0], a[fm][1], a[fm][2], a[fm][3],
                                b[bg][0], b[bg][1]);
                    }
                }
        }
    }
    __syncthreads();

    const int g = lane >> 2;
    const int cpair = (lane & 3) * 2;
    if (round_out) {
        __half* Ch = (__half*)CoutV;
        #pragma unroll
        for (int fm = 0; fm < 2; fm++)
            #pragma unroll
            for (int fn = 0; fn < 8; fn++) {
                int r = m0 + wm * 32 + fm * 16 + g;
                int c = n0 + wn * 64 + fn * 8 + cpair;
                *(uint32_t*)&Ch[(size_t)r * N + c] =
                    packh2(acc[fm][fn][0], acc[fm][fn][1]);
                *(uint32_t*)&Ch[(size_t)(r + 8) * N + c] =
                    packh2(acc[fm][fn][2], acc[fm][fn][3]);
            }
    } else {
        float* Cf = (float*)CoutV;
        #pragma unroll
        for (int fm = 0; fm < 2; fm++)
            #pragma unroll
            for (int fn = 0; fn < 8; fn++) {
                int r = m0 + wm * 32 + fm * 16 + g;
                int c = n0 + wn * 64 + fn * 8 + cpair;
                *(float2*)&Cf[(size_t)r * N + c] =
                    make_float2(acc[fm][fn][0], acc[fm][fn][1]);
                *(float2*)&Cf[(size_t)(r + 8) * N + c] =
                    make_float2(acc[fm][fn][2], acc[fm][fn][3]);
            }
    }
}

// ===========================================================================
// Flash sliding-window attention, fp16 mma m16n8k16, online softmax.
// One CTA = 64 queries of one (b,h); K and V double-buffered via cp.async;
// V consumed through ldmatrix.trans (no manual transpose). smem = 50KB.
// ===========================================================================
#define QT 64
#define KT 64
#define NKT 5
#define PPU 36            // P pitch in u32 (32 used + 4 pad)

// byte offsets
#define AQ   0            // 8192
#define AK   8192         // 2 x 8192
#define AV   24576        // 2 x 8192
#define AP   40960        // 64*36*4 = 9216
#define APM  50176        // 512
#define APS  50688        // 512
#define ATTN_SMEM_BYTES 51200

__global__ __launch_bounds__(256, 2) void attn_flash(const __half* __restrict__ qkv,
                                                     __half* __restrict__ y) {
    extern __shared__ char shm[];
    float* pmax = (float*)(shm + APM);
    float* psum = (float*)(shm + APS);
    uint32_t* Pu = (uint32_t*)(shm + AP);

    const int tid  = threadIdx.x;
    const int lane = tid & 31;
    const int wid  = tid >> 5;
    const int wm   = wid & 3;
    const int wn   = wid >> 2;
    const int q0 = blockIdx.x * QT;
    const int h  = blockIdx.y;
    const int b  = blockIdx.z;
    const int kstart = q0 - MEMW;
    const int kt0 = (q0 < MEMW) ? (MEMW - q0) / KT : 0;

    const __half* qbase = qkv + (size_t)b * TT * QKVN + h * DD;
    const __half* kbase = qbase + CC;
    const __half* vbase = qbase + 2 * CC;

    const uint32_t uQ = smem_u32(shm) + AQ;
    const uint32_t uK = smem_u32(shm) + AK;
    const uint32_t uV = smem_u32(shm) + AV;

    const int a_row = (lane & 7) + ((lane >> 3) & 1) * 8;
    const int a_col = (lane >> 4) * 16;
    const int b_row = (lane & 7) + (lane >> 4) * 8;
    const int b_col = ((lane >> 3) & 1) * 16;
    const int g  = lane >> 2;
    const int c2 = (lane & 3) * 2;
    const int r0 = wm * 16 + g;

    // ---- prologue: Q + K(kt0) + V(kt0), one group ----
    #pragma unroll
    for (int it = 0; it < 2; it++) {
        int idx = it * 256 + tid;
        int row = idx >> 3;
        int cc  = idx & 7;
        cp_async16(uQ + SW128((uint32_t)(row * 128 + cc * 16)),
                   &qbase[(size_t)(q0 + row) * QKVN + cc * 8]);
    }
    auto issue_kv = [&](int kt) {
        const uint32_t boff = (kt & 1) * 8192;
        const int kb = kstart + kt * KT;
        #pragma unroll
        for (int it = 0; it < 2; it++) {
            int idx = it * 256 + tid;
            int row = idx >> 3;
            int cc  = idx & 7;
            int gk  = kb + row;
            uint32_t sw = SW128((uint32_t)(row * 128 + cc * 16));
            int ok = (gk >= 0) ? 16 : 0;
            const __half* ks = (gk >= 0) ? &kbase[(size_t)gk * QKVN + cc * 8] : kbase;
            const __half* vs = (gk >= 0) ? &vbase[(size_t)gk * QKVN + cc * 8] : vbase;
            cp_async16_z(uK + boff + sw, ks, ok);
            cp_async16_z(uV + boff + sw, vs, ok);
        }
    };
    issue_kv(kt0);
    CP_COMMIT();

    float m_old0 = -1e30f, m_old1 = -1e30f;
    float srun0 = 0.f, srun1 = 0.f;
    float oacc[4][4];
    #pragma unroll
    for (int i = 0; i < 4; i++)
        #pragma unroll
        for (int j = 0; j < 4; j++) oacc[i][j] = 0.f;

    for (int kt = kt0; kt < NKT; kt++) {
        CP_WAIT(0);
        __syncthreads();                 // tile kt visible; prior readers done
        if (kt + 1 < NKT) { issue_kv(kt + 1); CP_COMMIT(); }

        const int kb = kstart + kt * KT;
        const uint32_t boff = (kt & 1) * 8192;

        // ---- scores: QK^T (64x64, k=d=64) ----
        float acc[4][4];
        #pragma unroll
        for (int i = 0; i < 4; i++)
            #pragma unroll
            for (int j = 0; j < 4; j++) acc[i][j] = 0.f;

        #pragma unroll
        for (int ks = 0; ks < 4; ks++) {
            uint32_t a[4];
            {
                int row = wm * 16 + a_row;
                LDSM_X4(a[0], a[1], a[2], a[3],
                        uQ + SW128((uint32_t)(row * 128 + ks * 32 + a_col)));
            }
            uint32_t bf[2][4];
            #pragma unroll
            for (int g2 = 0; g2 < 2; g2++) {
                int row = wn * 32 + g2 * 16 + b_row;
                LDSM_X4(bf[g2][0], bf[g2][1], bf[g2][2], bf[g2][3],
                        uK + boff + SW128((uint32_t)(row * 128 + ks * 32 + b_col)));
            }
            #pragma unroll
            for (int fn = 0; fn < 4; fn++) {
                const int bg = fn >> 1;
                if (fn & 1) {
                    MMA_F16(acc[fn], a[0], a[1], a[2], a[3], bf[bg][2], bf[bg][3]);
                } else {
                    MMA_F16(acc[fn], a[0], a[1], a[2], a[3], bf[bg][0], bf[bg][1]);
                }
            }
        }

        // ---- mask + scale + per-warp row max ----
        const int qi0 = q0 + r0;
        const int qi1 = qi0 + 8;
        float mx0 = -1e30f, mx1 = -1e30f;
        #pragma unroll
        for (int fn = 0; fn < 4; fn++) {
            int c  = wn * 32 + fn * 8 + c2;
            int kj = kb + c;
            #pragma unroll
            for (int jj = 0; jj < 2; jj++) {
                int k = kj + jj;
                bool ok0 = (k >= 0) && (k <= qi0) && (qi0 - k <= MEMW);
                bool ok1 = (k >= 0) && (k <= qi1) && (qi1 - k <= MEMW);
                acc[fn][jj]     = ok0 ? acc[fn][jj]     * 0.125f : -1e30f;
                acc[fn][2 + jj] = ok1 ? acc[fn][2 + jj] * 0.125f : -1e30f;
                mx0 = fmaxf(mx0, acc[fn][jj]);
                mx1 = fmaxf(mx1, acc[fn][2 + jj]);
            }
        }
        mx0 = fmaxf(mx0, __shfl_xor_sync(0xFFFFFFFF, mx0, 1));
        mx0 = fmaxf(mx0, __shfl_xor_sync(0xFFFFFFFF, mx0, 2));
        mx1 = fmaxf(mx1, __shfl_xor_sync(0xFFFFFFFF, mx1, 1));
        mx1 = fmaxf(mx1, __shfl_xor_sync(0xFFFFFFFF, mx1, 2));
        if ((lane & 3) == 0) {
            pmax[r0 * 2 + wn] = mx0;
            pmax[(r0 + 8) * 2 + wn] = mx1;
        }
        __syncthreads();

        // ---- online update + exp + P(half2) store + partial sums ----
        float m0 = fmaxf(m_old0, fmaxf(pmax[r0 * 2], pmax[r0 * 2 + 1]));
        float m1 = fmaxf(m_old1, fmaxf(pmax[(r0 + 8) * 2], pmax[(r0 + 8) * 2 + 1]));
        float f0 = __expf(m_old0 - m0);
        float f1 = __expf(m_old1 - m1);
        m_old0 = m0;
        m_old1 = m1;

        float s0 = 0.f, s1 = 0.f;
        #pragma unroll
        for (int fn = 0; fn < 4; fn++) {
            int cu = wn * 16 + fn * 4 + (lane & 3);   // u32 col
            float p00 = __expf(acc[fn][0] - m0);
            float p01 = __expf(acc[fn][1] - m0);
            float p10 = __expf(acc[fn][2] - m1);
            float p11 = __expf(acc[fn][3] - m1);
            Pu[r0 * PPU + cu] = packh2(p00, p01);
            Pu[(r0 + 8) * PPU + cu] = packh2(p10, p11);
            s0 += p00 + p01;
            s1 += p10 + p11;
        }
        s0 += __shfl_xor_sync(0xFFFFFFFF, s0, 1);
        s0 += __shfl_xor_sync(0xFFFFFFFF, s0, 2);
        s1 += __shfl_xor_sync(0xFFFFFFFF, s1, 1);
        s1 += __shfl_xor_sync(0xFFFFFFFF, s1, 2);
        if ((lane & 3) == 0) {
            psum[r0 * 2 + wn] = s0;
            psum[(r0 + 8) * 2 + wn] = s1;
        }
        #pragma unroll
        for (int fn = 0; fn < 4; fn++) {
            oacc[fn][0] *= f0;
            oacc[fn][1] *= f0;
            oacc[fn][2] *= f1;
            oacc[fn][3] *= f1;
        }
        __syncthreads();

        srun0 = srun0 * f0 + psum[r0 * 2] + psum[r0 * 2 + 1];
        srun1 = srun1 * f1 + psum[(r0 + 8) * 2] + psum[(r0 + 8) * 2 + 1];

        // ---- PV: O += P(64x64) x V(64x64), V via ldmatrix.trans ----
        #pragma unroll
        for (int ks = 0; ks < 4; ks++) {
            uint32_t a[4];
            {
                int base = ks * 8 + (lane & 3);
                a[0] = Pu[r0 * PPU + base];
                a[1] = Pu[(r0 + 8) * PPU + base];
                a[2] = Pu[r0 * PPU + base + 4];
                a[3] = Pu[(r0 + 8) * PPU + base + 4];
            }
            uint32_t bf[2][4];
            #pragma unroll
            for (int g2 = 0; g2 < 2; g2++) {
                int row = ks * 16 + (lane & 7) + ((lane >> 3) & 1) * 8;
                int bcol = wn * 64 + g2 * 32 + (lane >> 4) * 16;
                LDSM_X4T(bf[g2][0], bf[g2][1], bf[g2][2], bf[g2][3],
                         uV + boff + SW128((uint32_t)(row * 128 + bcol)));
            }
            #pragma unroll
            for (int fn = 0; fn < 4; fn++) {
                const int bg = fn >> 1;
                if (fn & 1) {
                    MMA_F16(oacc[fn], a[0], a[1], a[2], a[3], bf[bg][2], bf[bg][3]);
                } else {
                    MMA_F16(oacc[fn], a[0], a[1], a[2], a[3], bf[bg][0], bf[bg][1]);
                }
            }
        }
    }

    // ---- epilogue: normalize, fp16 store ----
    {
        float inv0 = 1.0f / srun0;
        float inv1 = 1.0f / srun1;
        #pragma unroll
        for (int fn = 0; fn < 4; fn++) {
            int col = wn * 32 + fn * 8 + c2;
            __half* p0 = &y[(size_t)(b * TT + q0 + r0) * CC + h * DD + col];
            __half* p1 = &y[(size_t)(b * TT + q0 + r0 + 8) * CC + h * DD + col];
            *(uint32_t*)p0 = packh2(oacc[fn][0] * inv0, oacc[fn][1] * inv0);
            *(uint32_t*)p1 = packh2(oacc[fn][2] * inv1, oacc[fn][3] * inv1);
        }
    }
}

// ===========================================================================
extern "C" void kernel_launch(void* const* d_in, const int* in_sizes, int n_in,
                              void* d_out, int out_size) {
    const float* x      = (const float*)d_in[0];
    const float* w_attn = (const float*)d_in[1];
    const float* w_proj = (const float*)d_in[2];
    float* out = (float*)d_out;

    __half *qkv = nullptr, *yb = nullptr, *xc = nullptr, *wac = nullptr, *wpc = nullptr;
    cudaGetSymbolAddress((void**)&qkv, g_qkv);
    cudaGetSymbolAddress((void**)&yb,  g_y);
    cudaGetSymbolAddress((void**)&xc,  g_xc);
    cudaGetSymbolAddress((void**)&wac, g_wac);
    cudaGetSymbolAddress((void**)&wpc, g_wpc);

    cudaFuncSetAttribute(attn_flash,
                         cudaFuncAttributeMaxDynamicSharedMemorySize, ATTN_SMEM_BYTES);
    cudaFuncSetAttribute(gemm_fp16,
                         cudaFuncAttributeMaxDynamicSharedMemorySize, GEMM_SMEM);

    // 0) fp16 pre-convert
    {
        int total8 = (XN + WAN + WPN) / 8;
        convert_kernel<<<(total8 + 255) / 256, 256>>>(x, w_attn, w_proj);
    }
    // 1) QKV projection (fp16 out)
    {
        dim3 grid(QKVN / GBN, M_TOT / GBM);
        gemm_fp16<<<grid, 256, GEMM_SMEM>>>(xc, wac, qkv, M_TOT, QKVN, CC, 1);
    }
    // 2) windowed attention -> y (fp16)
    {
        dim3 grid(TT / QT, HH, BB);
        attn_flash<<<grid, 256, ATTN_SMEM_BYTES>>>(qkv, yb);
    }
    // 3) output projection (fp32 out)
    {
        dim3 grid(CC / GBN, M_TOT / GBM);
        gemm_fp16<<<grid, 256, GEMM_SMEM>>>(yb, wpc, out, M_TOT, CC, CC, 0);
    }
}